// round 8
// baseline (speedup 1.0000x reference)
#include <cuda_runtime.h>
#include <cuda_bf16.h>
#include <math.h>
#include <stdint.h>

// Problem constants
#define B_  2
#define S_  2048
#define H_  2048
#define NH_ 16
#define HD_ 128
#define ROWS_ (B_ * S_)        // 4096
#define QKV_N (3 * H_)         // 6144

// ---------------- scratch (static device globals; no allocation) ----------------
__device__ float g_qkv[(size_t)ROWS_ * QKV_N];            // [4096, 6144]
__device__ float g_q[(size_t)B_ * NH_ * S_ * HD_];        // [b,h,s,d] tf32-rounded
__device__ float g_k[(size_t)B_ * NH_ * S_ * HD_];        // [b,h,s,d] tf32-rounded
__device__ float g_v[(size_t)B_ * NH_ * S_ * HD_];        // [b,h,d,s] tf32-rounded
__device__ float g_ctx[(size_t)ROWS_ * H_];               // [b*s, h*d] tf32-rounded
__device__ float g_hid_tf[(size_t)ROWS_ * H_];            // tf32-rounded A
__device__ float g_wct[(size_t)QKV_N * H_];               // Wc^T [6144][2048] tf32
__device__ float g_wpt[(size_t)H_ * H_];                  // Wp^T [2048][2048] tf32

// ---------------- helpers ----------------
__device__ __forceinline__ uint32_t f2tf(float x) {
    uint32_t r;
    asm("cvt.rna.tf32.f32 %0, %1;" : "=r"(r) : "f"(x));
    return r;
}
__device__ __forceinline__ float f2tff(float x) { return __uint_as_float(f2tf(x)); }

__device__ __forceinline__ void mma_tf32(float* c, const uint32_t* a, const uint32_t* b) {
    asm volatile(
        "mma.sync.aligned.m16n8k8.row.col.f32.tf32.tf32.f32 "
        "{%0,%1,%2,%3}, {%4,%5,%6,%7}, {%8,%9}, {%0,%1,%2,%3};\n"
        : "+f"(c[0]), "+f"(c[1]), "+f"(c[2]), "+f"(c[3])
        : "r"(a[0]), "r"(a[1]), "r"(a[2]), "r"(a[3]),
          "r"(b[0]), "r"(b[1]));
}
__device__ __forceinline__ void ldsm4(uint32_t* r, uint32_t addr) {
    asm volatile("ldmatrix.sync.aligned.m8n8.x4.shared.b16 {%0,%1,%2,%3}, [%4];"
        : "=r"(r[0]), "=r"(r[1]), "=r"(r[2]), "=r"(r[3]) : "r"(addr));
}
__device__ __forceinline__ uint32_t smem_u32(const void* p) {
    return (uint32_t)__cvta_generic_to_shared(p);
}
__device__ __forceinline__ void cp16(uint32_t dst, const void* src) {
    asm volatile("cp.async.cg.shared.global [%0], [%1], 16;" :: "r"(dst), "l"(src));
}
__device__ __forceinline__ void cp_commit() {
    asm volatile("cp.async.commit_group;");
}
template<int N> __device__ __forceinline__ void cp_wait() {
    asm volatile("cp.async.wait_group %0;" :: "n"(N));
}

// ---------------- tf32 pre-round (elementwise) ----------------
__global__ __launch_bounds__(256) void to_tf32k(const float* __restrict__ in,
                                                float* __restrict__ out, int n4)
{
    int i = blockIdx.x * 256 + threadIdx.x;
    if (i < n4) {
        float4 v = ((const float4*)in)[i];
        v.x = f2tff(v.x); v.y = f2tff(v.y); v.z = f2tff(v.z); v.w = f2tff(v.w);
        ((float4*)out)[i] = v;
    }
}

// ---------------- weight transpose + round: in[K][N] -> out[N][K] ----------------
__global__ __launch_bounds__(256) void wtrans(
    const float* __restrict__ in, float* __restrict__ out, int K, int N)
{
    __shared__ float t[32][33];
    const int k0 = blockIdx.x * 32, n0 = blockIdx.y * 32;
    const int x = threadIdx.x, y = threadIdx.y;   // 32 x 8
#pragma unroll
    for (int i = 0; i < 32; i += 8)
        t[y + i][x] = in[(size_t)(k0 + y + i) * N + n0 + x];
    __syncthreads();
#pragma unroll
    for (int i = 0; i < 32; i += 8)
        out[(size_t)(n0 + y + i) * K + k0 + x] = f2tff(t[x][y + i]);
}

// ---------------- TF32 GEMM: C[M,N] = A[M,K] @ Bt[N,K]^T + bias ----------------
// CTA tile 256(M) x 128(N), BK=32, 3 stages, 512 threads (16 warps, 4m x 4n),
// warp tile m64 x n32. As: [256][36], Bs: [128][36] per stage (k-minor, ldmatrix).
#define GSTR 36
#define GA_ST (256 * GSTR)          // 9216 words
#define GB_ST (128 * GSTR)          // 4608 words
#define G_ST  (GA_ST + GB_ST)       // 13824 words per stage
#define GEMM_SMEM (3 * G_ST * 4)    // 165888 B

__global__ __launch_bounds__(512) void gemm_tf32(
    const float* __restrict__ A, const float* __restrict__ Bt,
    const float* __restrict__ bias, float* __restrict__ C,
    int M, int N, int K)
{
    extern __shared__ float gsm[];
    const uint32_t as_u = smem_u32(gsm);

    const int tid = threadIdx.x;
    const int bx = blockIdx.x, by = blockIdx.y;
    const int warp = tid >> 5, lane = tid & 31;
    const int wm = (warp & 3) * 64;       // 4 warps in m
    const int wn = (warp >> 2) * 32;      // 4 warps in n
    const int lr = lane >> 2;
    const int lc = lane & 3;

    // ldmatrix lane geometry
    const int la_m = lane & 15;
    const int la_k = (lane >> 4) << 2;
    const int lb_r = (lane & 7) + ((lane >> 4) << 3);
    const int lb_c = ((lane >> 3) & 1) << 2;

    const uint32_t a_lane = as_u + (uint32_t)(((wm + la_m) * GSTR + la_k) * 4);
    const uint32_t b_lane = as_u + (uint32_t)(GA_ST * 4)
                          + (uint32_t)(((wn + lb_r) * GSTR + lb_c) * 4);

    const float* Ab = A + (size_t)(by * 256) * K;
    const float* Bb = Bt + (size_t)(bx * 128) * K;

    const int KT = K >> 5;   // k32 chunks

    // fill one k32 tile into stage st: A 256x32 (2048 chunks), B 128x32 (1024 chunks)
#define ISSUE_TILE(kt, st)                                                        \
    do {                                                                          \
        const float* Asrc = Ab + (kt) * 32;                                       \
        const float* Bsrc = Bb + (kt) * 32;                                       \
        uint32_t au = as_u + (uint32_t)((st) * G_ST * 4);                         \
        uint32_t bu = au + (uint32_t)(GA_ST * 4);                                 \
        _Pragma("unroll")                                                         \
        for (int i = 0; i < 4; i++) {                                             \
            int ch = tid + 512 * i;                                               \
            int r = ch >> 3, c = (ch & 7) << 2;                                   \
            cp16(au + (uint32_t)((r * GSTR + c) * 4), Asrc + (size_t)r * K + c);  \
        }                                                                         \
        _Pragma("unroll")                                                         \
        for (int i = 0; i < 2; i++) {                                             \
            int ch = tid + 512 * i;                                               \
            int r = ch >> 3, c = (ch & 7) << 2;                                   \
            cp16(bu + (uint32_t)((r * GSTR + c) * 4), Bsrc + (size_t)r * K + c);  \
        }                                                                         \
    } while (0)

    ISSUE_TILE(0, 0); cp_commit();
    ISSUE_TILE(1, 1); cp_commit();

    float c[4][4][4];
#pragma unroll
    for (int mt = 0; mt < 4; mt++)
#pragma unroll
        for (int nt = 0; nt < 4; nt++)
#pragma unroll
            for (int j = 0; j < 4; j++) c[mt][nt][j] = 0.f;

    for (int kt = 0; kt < KT; kt++) {
        cp_wait<1>();        // stage kt resident
        __syncthreads();
        if (kt + 2 < KT) { ISSUE_TILE(kt + 2, (kt + 2) % 3); }
        cp_commit();

        const uint32_t stoff = (uint32_t)((kt % 3) * G_ST * 4);
        const uint32_t a_st = a_lane + stoff;
        const uint32_t b_st = b_lane + stoff;

#pragma unroll
        for (int ks = 0; ks < 4; ks++) {
            const int kb = ks * 8;
            uint32_t af[4][4], bf[4][2];
#pragma unroll
            for (int mt = 0; mt < 4; mt++)
                ldsm4(af[mt], a_st + (uint32_t)((mt * 16 * GSTR + kb) * 4));
#pragma unroll
            for (int p = 0; p < 2; p++) {
                uint32_t r[4];
                ldsm4(r, b_st + (uint32_t)((p * 16 * GSTR + kb) * 4));
                bf[2 * p][0] = r[0]; bf[2 * p][1] = r[1];
                bf[2 * p + 1][0] = r[2]; bf[2 * p + 1][1] = r[3];
            }
#pragma unroll
            for (int mt = 0; mt < 4; mt++)
#pragma unroll
                for (int nt = 0; nt < 4; nt++)
                    mma_tf32(c[mt][nt], af[mt], bf[nt]);
        }
    }
#undef ISSUE_TILE

    // epilogue
#pragma unroll
    for (int mt = 0; mt < 4; mt++) {
        int row = by * 256 + wm + mt * 16 + lr;
#pragma unroll
        for (int nt = 0; nt < 4; nt++) {
            int col = bx * 128 + wn + nt * 8 + 2 * lc;
            float b0 = bias[col], b1 = bias[col + 1];
            float2 v0 = { c[mt][nt][0] + b0, c[mt][nt][1] + b1 };
            float2 v1 = { c[mt][nt][2] + b0, c[mt][nt][3] + b1 };
            *(float2*)(C + (size_t)row * N + col) = v0;
            *(float2*)(C + (size_t)(row + 8) * N + col) = v1;
        }
    }
}

// ---------------- RoPE + logn + split to [b,h,s,d] (Q,K only, tf32-rounded) ----------------
__global__ __launch_bounds__(256) void rope_split(
    const float* __restrict__ qkv,
    const float* __restrict__ cosb, const float* __restrict__ sinb,
    const float* __restrict__ logn,
    float* __restrict__ Q, float* __restrict__ Kt)
{
    int idx = blockIdx.x * blockDim.x + threadIdx.x;   // [b][s][h][d]
    if (idx >= B_ * S_ * NH_ * HD_) return;
    int d = idx & 127;
    int h = (idx >> 7) & 15;
    int s = (idx >> 11) & 2047;
    int b = idx >> 22;

    size_t row = (size_t)(b * S_ + s) * QKV_N;
    int col = h * HD_ + d;

    float cv = cosb[s * HD_ + d];
    float sv = sinb[s * HD_ + d];

    float qv = qkv[row + col];
    float kv = qkv[row + H_ + col];

    int   dro = (d < 64) ? (d + 64) : (d - 64);
    float sgn = (d < 64) ? -1.f : 1.f;
    float qo = qkv[row + h * HD_ + dro];
    float ko = qkv[row + H_ + h * HD_ + dro];

    float qr = qv * cv + sgn * qo * sv;
    float kr = kv * cv + sgn * ko * sv;

    float ln = logn[s] * 0.08838834764831845f;  // fold logn and 1/sqrt(HD) into q

    size_t oidx = (((size_t)(b * NH_ + h) * S_ + s) << 7) + d;
    Q[oidx]  = f2tff(qr * ln);
    Kt[oidx] = f2tff(kr);
}

// ---------------- V transpose: qkv[b,s,h,d] -> Vt[b,h,d,s] (tf32-rounded) ----------------
__global__ __launch_bounds__(256) void vtrans(
    const float* __restrict__ qkv, float* __restrict__ Vt)
{
    __shared__ float t[32][33];
    const int bh = blockIdx.z;
    const int b = bh >> 4, h = bh & 15;
    const int s0 = blockIdx.x * 32, d0 = blockIdx.y * 32;
    const int x = threadIdx.x, y = threadIdx.y;   // 32 x 8

#pragma unroll
    for (int i = 0; i < 32; i += 8)
        t[y + i][x] = qkv[(size_t)(b * S_ + s0 + y + i) * QKV_N + 2 * H_ + h * HD_ + d0 + x];
    __syncthreads();
#pragma unroll
    for (int i = 0; i < 32; i += 8)
        Vt[((size_t)bh * HD_ + d0 + y + i) * S_ + s0 + x] = f2tff(t[x][y + i]);
}

// ---------------- Flash attention: tf32 mma.sync + cp.async + ldmatrix ----------------
#define FBQ 128
#define FBKT 64
#define QSTR 132
#define KSTR 132
#define VSTR 68
#define PSTR 68
#define FK_STG (FBKT * KSTR)
#define OFF_K  (FBQ * QSTR)
#define OFF_V  (OFF_K + 2 * FK_STG)
#define OFF_P  (OFF_V + HD_ * VSTR)
#define FLASH_SMEM ((OFF_P + FBQ * PSTR) * 4)   // 204800 B

__global__ __launch_bounds__(256) void flash_tc(
    const float* __restrict__ Q, const float* __restrict__ K,
    const float* __restrict__ V, float* __restrict__ ctx)
{
    extern __shared__ float fsm[];
    uint32_t* Qs = (uint32_t*)fsm;
    float*    Ks = fsm + OFF_K;
    float*    Vs = fsm + OFF_V;               // [d=128][kv=64] pad->68
    uint32_t* Ps = (uint32_t*)(fsm + OFF_P);
    const uint32_t qs_u = smem_u32(Qs);
    const uint32_t ks_u = smem_u32(Ks);
    const uint32_t vs_u = smem_u32(Vs);
    const uint32_t ps_u = smem_u32(Ps);

    const int qt = (S_ / FBQ - 1) - blockIdx.x;   // heavy tiles first
    const int bh = blockIdx.y;
    const int tid = threadIdx.x;
    const int warp = tid >> 5, lane = tid & 31;
    const int lr = lane >> 2;
    const int lc = lane & 3;

    const int la_m = lane & 15;
    const int la_k = (lane >> 4) << 2;
    const int lb_r = (lane & 7) + ((lane >> 4) << 3);
    const int lb_c = ((lane >> 3) & 1) << 2;

    const uint32_t q_lane = qs_u + (uint32_t)(((warp * 16 + la_m) * QSTR + la_k) * 4);
    const uint32_t p_lane = ps_u + (uint32_t)(((warp * 16 + la_m) * PSTR + la_k) * 4);

    const float* Qb = Q + ((size_t)bh * S_ + qt * FBQ) * HD_;
    const float* Kb = K + (size_t)bh * S_ * HD_;
    const float* Vb = V + (size_t)bh * HD_ * S_;   // [d][s]

    for (int t = tid; t < FBQ * (HD_ / 4); t += 256) {
        int r = t >> 5, c4 = (t & 31) << 2;
        *(uint4*)&Qs[r * QSTR + c4] = *(const uint4*)(Qb + (size_t)r * HD_ + c4);
    }

    const int nkt = 2 * qt + 2;

#define ISSUE_K(kt)                                                               \
    do {                                                                          \
        const float* src = Kb + (size_t)(kt) * FBKT * HD_;                        \
        uint32_t dst = ks_u + (uint32_t)(((kt) & 1) * FK_STG * 4);                \
        _Pragma("unroll")                                                         \
        for (int i = 0; i < 8; i++) {                                             \
            int ch = tid + 256 * i;                                               \
            int r = ch >> 5, c4 = (ch & 31) << 2;                                 \
            cp16(dst + (uint32_t)((r * KSTR + c4) * 4), src + (size_t)r * HD_ + c4); \
        }                                                                         \
    } while (0)
#define ISSUE_V(kt)                                                               \
    do {                                                                          \
        const float* src = Vb + (size_t)(kt) * FBKT;                              \
        _Pragma("unroll")                                                         \
        for (int i = 0; i < 8; i++) {                                             \
            int ch = tid + 256 * i;                                               \
            int r = ch >> 4, c4 = (ch & 15) << 2;                                 \
            cp16(vs_u + (uint32_t)((r * VSTR + c4) * 4), src + (size_t)r * S_ + c4); \
        }                                                                         \
    } while (0)

    ISSUE_K(0);
    cp_commit();

    float m0 = -1e30f, m1 = -1e30f;
    float l0 = 0.f, l1 = 0.f;
    float o[16][4];
#pragma unroll
    for (int nt = 0; nt < 16; nt++)
#pragma unroll
        for (int j = 0; j < 4; j++) o[nt][j] = 0.f;

    const int r0 = warp * 16 + lr;
    const int g0 = qt * FBQ + r0;
    const int g1 = g0 + 8;

    for (int kt = 0; kt < nkt; kt++) {
        ISSUE_V(kt);
        cp_commit();
        if (kt + 1 < nkt) { ISSUE_K(kt + 1); }
        cp_commit();

        cp_wait<2>();
        __syncthreads();

        const uint32_t kst_u = ks_u + (uint32_t)((kt & 1) * FK_STG * 4);

        float s[8][4];
#pragma unroll
        for (int nt = 0; nt < 8; nt++)
#pragma unroll
            for (int j = 0; j < 4; j++) s[nt][j] = 0.f;

#pragma unroll
        for (int ksx = 0; ksx < 16; ksx++) {
            const int kb = ksx * 8;
            uint32_t a[4];
            ldsm4(a, q_lane + (uint32_t)(kb * 4));
#pragma unroll
            for (int p = 0; p < 4; p++) {
                uint32_t r[4];
                ldsm4(r, kst_u + (uint32_t)(((p * 16 + lb_r) * KSTR + kb + lb_c) * 4));
                mma_tf32(s[2 * p], a, r);
                mma_tf32(s[2 * p + 1], a, r + 2);
            }
        }

        if (kt * FBKT + FBKT - 1 > qt * FBQ + warp * 16) {
#pragma unroll
            for (int nt = 0; nt < 8; nt++) {
                int colb = kt * FBKT + nt * 8 + 2 * lc;
                if (colb > g0)     s[nt][0] = -1e30f;
                if (colb + 1 > g0) s[nt][1] = -1e30f;
                if (colb > g1)     s[nt][2] = -1e30f;
                if (colb + 1 > g1) s[nt][3] = -1e30f;
            }
        }

        float mx0 = -1e30f, mx1 = -1e30f;
#pragma unroll
        for (int nt = 0; nt < 8; nt++) {
            mx0 = fmaxf(mx0, fmaxf(s[nt][0], s[nt][1]));
            mx1 = fmaxf(mx1, fmaxf(s[nt][2], s[nt][3]));
        }
        mx0 = fmaxf(mx0, __shfl_xor_sync(0xffffffffu, mx0, 1));
        mx0 = fmaxf(mx0, __shfl_xor_sync(0xffffffffu, mx0, 2));
        mx1 = fmaxf(mx1, __shfl_xor_sync(0xffffffffu, mx1, 1));
        mx1 = fmaxf(mx1, __shfl_xor_sync(0xffffffffu, mx1, 2));

        float nm0 = fmaxf(m0, mx0), nm1 = fmaxf(m1, mx1);
        float al0 = __expf(m0 - nm0), al1 = __expf(m1 - nm1);
        m0 = nm0; m1 = nm1;

        float sum0 = 0.f, sum1 = 0.f;
#pragma unroll
        for (int nt = 0; nt < 8; nt++) {
            s[nt][0] = __expf(s[nt][0] - nm0);
            s[nt][1] = __expf(s[nt][1] - nm0);
            s[nt][2] = __expf(s[nt][2] - nm1);
            s[nt][3] = __expf(s[nt][3] - nm1);
            sum0 += s[nt][0] + s[nt][1];
            sum1 += s[nt][2] + s[nt][3];
        }
        sum0 += __shfl_xor_sync(0xffffffffu, sum0, 1);
        sum0 += __shfl_xor_sync(0xffffffffu, sum0, 2);
        sum1 += __shfl_xor_sync(0xffffffffu, sum1, 1);
        sum1 += __shfl_xor_sync(0xffffffffu, sum1, 2);
        l0 = l0 * al0 + sum0;
        l1 = l1 * al1 + sum1;

#pragma unroll
        for (int nt = 0; nt < 16; nt++) {
            o[nt][0] *= al0; o[nt][1] *= al0;
            o[nt][2] *= al1; o[nt][3] *= al1;
        }

#pragma unroll
        for (int nt = 0; nt < 8; nt++) {
            int colp = nt * 8 + 2 * lc;
            Ps[r0 * PSTR + colp]           = f2tf(s[nt][0]);
            Ps[r0 * PSTR + colp + 1]       = f2tf(s[nt][1]);
            Ps[(r0 + 8) * PSTR + colp]     = f2tf(s[nt][2]);
            Ps[(r0 + 8) * PSTR + colp + 1] = f2tf(s[nt][3]);
        }
        __syncwarp();

        cp_wait<1>();
        __syncthreads();

#pragma unroll
        for (int ksx = 0; ksx < 8; ksx++) {
            const int kb = ksx * 8;
            uint32_t a[4];
            ldsm4(a, p_lane + (uint32_t)(kb * 4));
#pragma unroll
            for (int p = 0; p < 8; p++) {
                uint32_t r[4];
                ldsm4(r, vs_u + (uint32_t)(((p * 16 + lb_r) * VSTR + kb + lb_c) * 4));
                mma_tf32(o[2 * p], a, r);
                mma_tf32(o[2 * p + 1], a, r + 2);
            }
        }
        __syncthreads();
    }
#undef ISSUE_K
#undef ISSUE_V

    float il0 = 1.f / l0, il1 = 1.f / l1;
    int b = bh >> 4, h = bh & 15;
    float* out0 = ctx + (size_t)(b * S_ + g0) * H_ + h * HD_;
    float* out1 = ctx + (size_t)(b * S_ + g1) * H_ + h * HD_;
#pragma unroll
    for (int nt = 0; nt < 16; nt++) {
        int col = nt * 8 + 2 * lc;
        float2 v0 = { f2tff(o[nt][0] * il0), f2tff(o[nt][1] * il0) };
        float2 v1 = { f2tff(o[nt][2] * il1), f2tff(o[nt][3] * il1) };
        *(float2*)(out0 + col) = v0;
        *(float2*)(out1 + col) = v1;
    }
}

// ---------------- launch ----------------
extern "C" void kernel_launch(void* const* d_in, const int* in_sizes, int n_in,
                              void* d_out, int out_size)
{
    const float* hidden = (const float*)d_in[0];
    const float* cosb   = (const float*)d_in[1];
    const float* sinb   = (const float*)d_in[2];
    // d_in[3]: attention_mask (pure causal -> implemented directly)
    const float* logn   = (const float*)d_in[4];
    const float* Wc     = (const float*)d_in[5];
    const float* bc     = (const float*)d_in[6];
    const float* Wp     = (const float*)d_in[7];
    const float* bp     = (const float*)d_in[8];
    float* out = (float*)d_out;

    float *qkv, *Q, *Kt, *Vt, *ctx, *hid_tf, *wct, *wpt;
    cudaGetSymbolAddress((void**)&qkv,    g_qkv);
    cudaGetSymbolAddress((void**)&Q,      g_q);
    cudaGetSymbolAddress((void**)&Kt,     g_k);
    cudaGetSymbolAddress((void**)&Vt,     g_v);
    cudaGetSymbolAddress((void**)&ctx,    g_ctx);
    cudaGetSymbolAddress((void**)&hid_tf, g_hid_tf);
    cudaGetSymbolAddress((void**)&wct,    g_wct);
    cudaGetSymbolAddress((void**)&wpt,    g_wpt);

    cudaFuncSetAttribute(gemm_tf32,
                         cudaFuncAttributeMaxDynamicSharedMemorySize, GEMM_SMEM);
    cudaFuncSetAttribute(flash_tc,
                         cudaFuncAttributeMaxDynamicSharedMemorySize, FLASH_SMEM);

    // 0) pre-round A; transpose+round weights to [N][K]
    {
        int n4h = (ROWS_ * H_) / 4;
        to_tf32k<<<(n4h + 255) / 256, 256>>>(hidden, hid_tf, n4h);
        wtrans<<<dim3(H_ / 32, QKV_N / 32), dim3(32, 8)>>>(Wc, wct, H_, QKV_N);
        wtrans<<<dim3(H_ / 32, H_ / 32), dim3(32, 8)>>>(Wp, wpt, H_, H_);
    }

    // 1) qkv = hidden @ Wc + bc   [4096,6144]
    gemm_tf32<<<dim3(QKV_N / 128, ROWS_ / 256), 512, GEMM_SMEM>>>(
        hid_tf, wct, bc, qkv, ROWS_, QKV_N, H_);

    // 2) rope + logn -> Q,K [b,h,s,d];  V transpose -> [b,h,d,s]
    {
        int total = B_ * S_ * NH_ * HD_;
        rope_split<<<(total + 255) / 256, 256>>>(qkv, cosb, sinb, logn, Q, Kt);
        vtrans<<<dim3(S_ / 32, HD_ / 32, B_ * NH_), dim3(32, 8)>>>(qkv, Vt);
    }

    // 3) flash attention -> ctx [4096, 2048]
    flash_tc<<<dim3(S_ / FBQ, B_ * NH_), 256, FLASH_SMEM>>>(Q, Kt, Vt, ctx);

    // 4) out = ctx @ Wp + bp      [4096,2048]
    gemm_tf32<<<dim3(H_ / 128, ROWS_ / 256), 512, GEMM_SMEM>>>(
        ctx, wpt, bp, out, ROWS_, H_, H_);
}

// round 9
// speedup vs baseline: 1.0905x; 1.0905x over previous
#include <cuda_runtime.h>
#include <cuda_bf16.h>
#include <math.h>
#include <stdint.h>

// Problem constants
#define B_  2
#define S_  2048
#define H_  2048
#define NH_ 16
#define HD_ 128
#define ROWS_ (B_ * S_)        // 4096
#define QKV_N (3 * H_)         // 6144

// ---------------- scratch (static device globals; no allocation) ----------------
__device__ float g_qkv[(size_t)ROWS_ * QKV_N];            // [4096, 6144]
__device__ float g_q[(size_t)B_ * NH_ * S_ * HD_];        // [b,h,s,d] tf32-rounded
__device__ float g_k[(size_t)B_ * NH_ * S_ * HD_];        // [b,h,s,d] tf32-rounded
__device__ float g_v[(size_t)B_ * NH_ * S_ * HD_];        // [b,h,d,s] tf32-rounded
__device__ float g_ctx[(size_t)ROWS_ * H_];               // [b*s, h*d] tf32-rounded
__device__ float g_hid_tf[(size_t)ROWS_ * H_];            // tf32-rounded A
__device__ float g_wct[(size_t)QKV_N * H_];               // Wc^T [6144][2048] tf32
__device__ float g_wpt[(size_t)H_ * H_];                  // Wp^T [2048][2048] tf32

// ---------------- helpers ----------------
__device__ __forceinline__ uint32_t f2tf(float x) {
    uint32_t r;
    asm("cvt.rna.tf32.f32 %0, %1;" : "=r"(r) : "f"(x));
    return r;
}
__device__ __forceinline__ float f2tff(float x) { return __uint_as_float(f2tf(x)); }

__device__ __forceinline__ void mma_tf32(float* c, const uint32_t* a, const uint32_t* b) {
    asm volatile(
        "mma.sync.aligned.m16n8k8.row.col.f32.tf32.tf32.f32 "
        "{%0,%1,%2,%3}, {%4,%5,%6,%7}, {%8,%9}, {%0,%1,%2,%3};\n"
        : "+f"(c[0]), "+f"(c[1]), "+f"(c[2]), "+f"(c[3])
        : "r"(a[0]), "r"(a[1]), "r"(a[2]), "r"(a[3]),
          "r"(b[0]), "r"(b[1]));
}
__device__ __forceinline__ void ldsm4(uint32_t* r, uint32_t addr) {
    asm volatile("ldmatrix.sync.aligned.m8n8.x4.shared.b16 {%0,%1,%2,%3}, [%4];"
        : "=r"(r[0]), "=r"(r[1]), "=r"(r[2]), "=r"(r[3]) : "r"(addr));
}
__device__ __forceinline__ uint32_t smem_u32(const void* p) {
    return (uint32_t)__cvta_generic_to_shared(p);
}
__device__ __forceinline__ void cp16(uint32_t dst, const void* src) {
    asm volatile("cp.async.cg.shared.global [%0], [%1], 16;" :: "r"(dst), "l"(src));
}
__device__ __forceinline__ void cp_commit() {
    asm volatile("cp.async.commit_group;");
}
template<int N> __device__ __forceinline__ void cp_wait() {
    asm volatile("cp.async.wait_group %0;" :: "n"(N));
}

// ---------------- tf32 pre-round (elementwise) ----------------
__global__ __launch_bounds__(256) void to_tf32k(const float* __restrict__ in,
                                                float* __restrict__ out, int n4)
{
    int i = blockIdx.x * 256 + threadIdx.x;
    if (i < n4) {
        float4 v = ((const float4*)in)[i];
        v.x = f2tff(v.x); v.y = f2tff(v.y); v.z = f2tff(v.z); v.w = f2tff(v.w);
        ((float4*)out)[i] = v;
    }
}

// ---------------- weight transpose + round: in[K][N] -> out[N][K] ----------------
__global__ __launch_bounds__(256) void wtrans(
    const float* __restrict__ in, float* __restrict__ out, int K, int N)
{
    __shared__ float t[32][33];
    const int k0 = blockIdx.x * 32, n0 = blockIdx.y * 32;
    const int x = threadIdx.x, y = threadIdx.y;   // 32 x 8
#pragma unroll
    for (int i = 0; i < 32; i += 8)
        t[y + i][x] = in[(size_t)(k0 + y + i) * N + n0 + x];
    __syncthreads();
#pragma unroll
    for (int i = 0; i < 32; i += 8)
        out[(size_t)(n0 + y + i) * K + k0 + x] = f2tff(t[x][y + i]);
}

// ---------------- TF32 GEMM (R7 config): C = A @ Bt^T + bias ----------------
// CTA tile 128x128, BK=32, 3 stages, 256 threads (8 warps, 2m x 4n), warp m64 x n32.
#define GSTR 36
#define GT_ST (128 * GSTR)          // 4608 words per operand per stage
#define G_ST  (2 * GT_ST)           // 9216 words per stage
#define GEMM_SMEM (3 * G_ST * 4)    // 110592 B

__global__ __launch_bounds__(256) void gemm_tf32(
    const float* __restrict__ A, const float* __restrict__ Bt,
    const float* __restrict__ bias, float* __restrict__ C,
    int M, int N, int K)
{
    extern __shared__ float gsm[];
    const uint32_t as_u = smem_u32(gsm);

    const int tid = threadIdx.x;
    const int bx = blockIdx.x, by = blockIdx.y;
    const int warp = tid >> 5, lane = tid & 31;
    const int wm = (warp & 1) * 64;
    const int wn = (warp >> 1) * 32;
    const int lr = lane >> 2;
    const int lc = lane & 3;

    const int la_m = lane & 15;
    const int la_k = (lane >> 4) << 2;
    const int lb_r = (lane & 7) + ((lane >> 4) << 3);
    const int lb_c = ((lane >> 3) & 1) << 2;

    const uint32_t a_lane = as_u + (uint32_t)(((wm + la_m) * GSTR + la_k) * 4);
    const uint32_t b_lane = as_u + (uint32_t)(GT_ST * 4)
                          + (uint32_t)(((wn + lb_r) * GSTR + lb_c) * 4);

    const float* Ab = A + (size_t)(by * 128) * K;
    const float* Bb = Bt + (size_t)(bx * 128) * K;

    const int KT = K >> 5;

#define ISSUE_TILE(kt, st)                                                        \
    do {                                                                          \
        const float* Asrc = Ab + (kt) * 32;                                       \
        const float* Bsrc = Bb + (kt) * 32;                                       \
        uint32_t au = as_u + (uint32_t)((st) * G_ST * 4);                         \
        uint32_t bu = au + (uint32_t)(GT_ST * 4);                                 \
        _Pragma("unroll")                                                         \
        for (int i = 0; i < 4; i++) {                                             \
            int ch = tid + 256 * i;                                               \
            int r = ch >> 3, c = (ch & 7) << 2;                                   \
            cp16(au + (uint32_t)((r * GSTR + c) * 4), Asrc + (size_t)r * K + c);  \
            cp16(bu + (uint32_t)((r * GSTR + c) * 4), Bsrc + (size_t)r * K + c);  \
        }                                                                         \
    } while (0)

    ISSUE_TILE(0, 0); cp_commit();
    ISSUE_TILE(1, 1); cp_commit();

    float c[4][4][4];
#pragma unroll
    for (int mt = 0; mt < 4; mt++)
#pragma unroll
        for (int nt = 0; nt < 4; nt++)
#pragma unroll
            for (int j = 0; j < 4; j++) c[mt][nt][j] = 0.f;

    for (int kt = 0; kt < KT; kt++) {
        cp_wait<1>();
        __syncthreads();
        if (kt + 2 < KT) { ISSUE_TILE(kt + 2, (kt + 2) % 3); }
        cp_commit();

        const uint32_t stoff = (uint32_t)((kt % 3) * G_ST * 4);
        const uint32_t a_st = a_lane + stoff;
        const uint32_t b_st = b_lane + stoff;

#pragma unroll
        for (int ks = 0; ks < 4; ks++) {
            const int kb = ks * 8;
            uint32_t af[4][4], bf[4][2];
#pragma unroll
            for (int mt = 0; mt < 4; mt++)
                ldsm4(af[mt], a_st + (uint32_t)((mt * 16 * GSTR + kb) * 4));
#pragma unroll
            for (int p = 0; p < 2; p++) {
                uint32_t r[4];
                ldsm4(r, b_st + (uint32_t)((p * 16 * GSTR + kb) * 4));
                bf[2 * p][0] = r[0]; bf[2 * p][1] = r[1];
                bf[2 * p + 1][0] = r[2]; bf[2 * p + 1][1] = r[3];
            }
#pragma unroll
            for (int mt = 0; mt < 4; mt++)
#pragma unroll
                for (int nt = 0; nt < 4; nt++)
                    mma_tf32(c[mt][nt], af[mt], bf[nt]);
        }
    }
#undef ISSUE_TILE

#pragma unroll
    for (int mt = 0; mt < 4; mt++) {
        int row = by * 128 + wm + mt * 16 + lr;
#pragma unroll
        for (int nt = 0; nt < 4; nt++) {
            int col = bx * 128 + wn + nt * 8 + 2 * lc;
            float b0 = bias[col], b1 = bias[col + 1];
            float2 v0 = { c[mt][nt][0] + b0, c[mt][nt][1] + b1 };
            float2 v1 = { c[mt][nt][2] + b0, c[mt][nt][3] + b1 };
            *(float2*)(C + (size_t)row * N + col) = v0;
            *(float2*)(C + (size_t)(row + 8) * N + col) = v1;
        }
    }
}

// ---------------- RoPE + logn + split to [b,h,s,d] (Q,K only, tf32-rounded) ----------------
__global__ __launch_bounds__(256) void rope_split(
    const float* __restrict__ qkv,
    const float* __restrict__ cosb, const float* __restrict__ sinb,
    const float* __restrict__ logn,
    float* __restrict__ Q, float* __restrict__ Kt)
{
    int idx = blockIdx.x * blockDim.x + threadIdx.x;   // [b][s][h][d]
    if (idx >= B_ * S_ * NH_ * HD_) return;
    int d = idx & 127;
    int h = (idx >> 7) & 15;
    int s = (idx >> 11) & 2047;
    int b = idx >> 22;

    size_t row = (size_t)(b * S_ + s) * QKV_N;
    int col = h * HD_ + d;

    float cv = cosb[s * HD_ + d];
    float sv = sinb[s * HD_ + d];

    float qv = qkv[row + col];
    float kv = qkv[row + H_ + col];

    int   dro = (d < 64) ? (d + 64) : (d - 64);
    float sgn = (d < 64) ? -1.f : 1.f;
    float qo = qkv[row + h * HD_ + dro];
    float ko = qkv[row + H_ + h * HD_ + dro];

    float qr = qv * cv + sgn * qo * sv;
    float kr = kv * cv + sgn * ko * sv;

    float ln = logn[s] * 0.08838834764831845f;  // fold logn and 1/sqrt(HD) into q

    size_t oidx = (((size_t)(b * NH_ + h) * S_ + s) << 7) + d;
    Q[oidx]  = f2tff(qr * ln);
    Kt[oidx] = f2tff(kr);
}

// ---------------- V transpose: qkv[b,s,h,d] -> Vt[b,h,d,s] (tf32-rounded) ----------------
__global__ __launch_bounds__(256) void vtrans(
    const float* __restrict__ qkv, float* __restrict__ Vt)
{
    __shared__ float t[32][33];
    const int bh = blockIdx.z;
    const int b = bh >> 4, h = bh & 15;
    const int s0 = blockIdx.x * 32, d0 = blockIdx.y * 32;
    const int x = threadIdx.x, y = threadIdx.y;   // 32 x 8

#pragma unroll
    for (int i = 0; i < 32; i += 8)
        t[y + i][x] = qkv[(size_t)(b * S_ + s0 + y + i) * QKV_N + 2 * H_ + h * HD_ + d0 + x];
    __syncthreads();
#pragma unroll
    for (int i = 0; i < 32; i += 8)
        Vt[((size_t)bh * HD_ + d0 + y + i) * S_ + s0 + x] = f2tff(t[x][y + i]);
}

// ---------------- Flash attention v2: Q in regs, K+V double-buffered, 2 bars/tile ----------------
#define FBQ 128
#define FBKT 64
#define KSTR 132
#define VSTR 68
#define PSTR 68
#define FK_ST (FBKT * KSTR)            // 8448 words per K stage
#define FV_ST (HD_ * VSTR)             // 8704 words per V stage
#define OFF_V (2 * FK_ST)              // 16896
#define OFF_P (OFF_V + 2 * FV_ST)      // 34304
#define FLASH_SMEM ((OFF_P + FBQ * PSTR) * 4)   // 172032 B

__global__ __launch_bounds__(256) void flash_tc(
    const float* __restrict__ Q, const float* __restrict__ K,
    const float* __restrict__ V, float* __restrict__ ctx)
{
    extern __shared__ float fsm[];
    uint32_t* Ps = (uint32_t*)(fsm + OFF_P);
    const uint32_t ks_u = smem_u32(fsm);
    const uint32_t vs_u = ks_u + (uint32_t)(OFF_V * 4);
    const uint32_t ps_u = smem_u32(Ps);

    const int qt = (S_ / FBQ - 1) - blockIdx.x;   // heavy tiles first
    const int bh = blockIdx.y;
    const int tid = threadIdx.x;
    const int warp = tid >> 5, lane = tid & 31;
    const int lr = lane >> 2;
    const int lc = lane & 3;

    const int la_m = lane & 15;
    const int la_k = (lane >> 4) << 2;
    const int lb_r = (lane & 7) + ((lane >> 4) << 3);
    const int lb_c = ((lane >> 3) & 1) << 2;

    const uint32_t p_lane = ps_u + (uint32_t)(((warp * 16 + la_m) * PSTR + la_k) * 4);

    const float* Qb = Q + ((size_t)bh * S_ + qt * FBQ) * HD_;
    const float* Kb = K + (size_t)bh * S_ * HD_;
    const float* Vb = V + (size_t)bh * HD_ * S_;   // [d][s]

    // ---- stage Q through (K-region) smem once; ldmatrix into registers ----
    for (int t = tid; t < FBQ * (HD_ / 4); t += 256) {
        int r = t >> 5, c4 = (t & 31) << 2;
        *(uint4*)(fsm + r * KSTR + c4) = *(const uint4*)(Qb + (size_t)r * HD_ + c4);
    }
    __syncthreads();
    uint32_t qf[16][4];
    {
        const uint32_t q_lane = ks_u + (uint32_t)(((warp * 16 + la_m) * KSTR + la_k) * 4);
#pragma unroll
        for (int ks = 0; ks < 16; ks++)
            ldsm4(qf[ks], q_lane + (uint32_t)(ks * 8 * 4));
    }
    __syncthreads();

    const int nkt = 2 * qt + 2;

    // one group = K(kt) + V(kt) into stage (kt&1)
#define ISSUE_KV(kt)                                                              \
    do {                                                                          \
        const float* ksrc = Kb + (size_t)(kt) * FBKT * HD_;                       \
        const float* vsrc = Vb + (size_t)(kt) * FBKT;                             \
        uint32_t kdst = ks_u + (uint32_t)(((kt) & 1) * FK_ST * 4);                \
        uint32_t vdst = vs_u + (uint32_t)(((kt) & 1) * FV_ST * 4);                \
        _Pragma("unroll")                                                         \
        for (int i = 0; i < 8; i++) {                                             \
            int ch = tid + 256 * i;                                               \
            int kr = ch >> 5, kc = (ch & 31) << 2;                                \
            cp16(kdst + (uint32_t)((kr * KSTR + kc) * 4),                         \
                 ksrc + (size_t)kr * HD_ + kc);                                   \
            int vr = ch >> 4, vc = (ch & 15) << 2;                                \
            cp16(vdst + (uint32_t)((vr * VSTR + vc) * 4),                         \
                 vsrc + (size_t)vr * S_ + vc);                                    \
        }                                                                         \
    } while (0)

    ISSUE_KV(0);
    cp_commit();

    float m0 = -1e30f, m1 = -1e30f;
    float l0 = 0.f, l1 = 0.f;
    float o[16][4];
#pragma unroll
    for (int nt = 0; nt < 16; nt++)
#pragma unroll
        for (int j = 0; j < 4; j++) o[nt][j] = 0.f;

    const int r0 = warp * 16 + lr;
    const int g0 = qt * FBQ + r0;
    const int g1 = g0 + 8;

    for (int kt = 0; kt < nkt; kt++) {
        if (kt + 1 < nkt) {
            ISSUE_KV(kt + 1);
            cp_commit();
            cp_wait<1>();            // group kt complete
        } else {
            cp_wait<0>();
        }
        __syncthreads();

        const uint32_t kst_u = ks_u + (uint32_t)((kt & 1) * FK_ST * 4);
        const uint32_t vst_u = vs_u + (uint32_t)((kt & 1) * FV_ST * 4);

        // ---- S = Q @ K^T ----
        float s[8][4];
#pragma unroll
        for (int nt = 0; nt < 8; nt++)
#pragma unroll
            for (int j = 0; j < 4; j++) s[nt][j] = 0.f;

#pragma unroll
        for (int ksx = 0; ksx < 16; ksx++) {
            const int kb = ksx * 8;
#pragma unroll
            for (int p = 0; p < 4; p++) {
                uint32_t r[4];
                ldsm4(r, kst_u + (uint32_t)(((p * 16 + lb_r) * KSTR + kb + lb_c) * 4));
                mma_tf32(s[2 * p], qf[ksx], r);
                mma_tf32(s[2 * p + 1], qf[ksx], r + 2);
            }
        }

        // ---- causal mask ----
        if (kt * FBKT + FBKT - 1 > qt * FBQ + warp * 16) {
#pragma unroll
            for (int nt = 0; nt < 8; nt++) {
                int colb = kt * FBKT + nt * 8 + 2 * lc;
                if (colb > g0)     s[nt][0] = -1e30f;
                if (colb + 1 > g0) s[nt][1] = -1e30f;
                if (colb > g1)     s[nt][2] = -1e30f;
                if (colb + 1 > g1) s[nt][3] = -1e30f;
            }
        }

        // ---- online softmax ----
        float mx0 = -1e30f, mx1 = -1e30f;
#pragma unroll
        for (int nt = 0; nt < 8; nt++) {
            mx0 = fmaxf(mx0, fmaxf(s[nt][0], s[nt][1]));
            mx1 = fmaxf(mx1, fmaxf(s[nt][2], s[nt][3]));
        }
        mx0 = fmaxf(mx0, __shfl_xor_sync(0xffffffffu, mx0, 1));
        mx0 = fmaxf(mx0, __shfl_xor_sync(0xffffffffu, mx0, 2));
        mx1 = fmaxf(mx1, __shfl_xor_sync(0xffffffffu, mx1, 1));
        mx1 = fmaxf(mx1, __shfl_xor_sync(0xffffffffu, mx1, 2));

        float nm0 = fmaxf(m0, mx0), nm1 = fmaxf(m1, mx1);
        float al0 = __expf(m0 - nm0), al1 = __expf(m1 - nm1);
        m0 = nm0; m1 = nm1;

        float sum0 = 0.f, sum1 = 0.f;
#pragma unroll
        for (int nt = 0; nt < 8; nt++) {
            s[nt][0] = __expf(s[nt][0] - nm0);
            s[nt][1] = __expf(s[nt][1] - nm0);
            s[nt][2] = __expf(s[nt][2] - nm1);
            s[nt][3] = __expf(s[nt][3] - nm1);
            sum0 += s[nt][0] + s[nt][1];
            sum1 += s[nt][2] + s[nt][3];
        }
        sum0 += __shfl_xor_sync(0xffffffffu, sum0, 1);
        sum0 += __shfl_xor_sync(0xffffffffu, sum0, 2);
        sum1 += __shfl_xor_sync(0xffffffffu, sum1, 1);
        sum1 += __shfl_xor_sync(0xffffffffu, sum1, 2);
        l0 = l0 * al0 + sum0;
        l1 = l1 * al1 + sum1;

#pragma unroll
        for (int nt = 0; nt < 16; nt++) {
            o[nt][0] *= al0; o[nt][1] *= al0;
            o[nt][2] *= al1; o[nt][3] *= al1;
        }

        // ---- store P (tf32), warp-private rows ----
#pragma unroll
        for (int nt = 0; nt < 8; nt++) {
            int colp = nt * 8 + 2 * lc;
            Ps[r0 * PSTR + colp]           = f2tf(s[nt][0]);
            Ps[r0 * PSTR + colp + 1]       = f2tf(s[nt][1]);
            Ps[(r0 + 8) * PSTR + colp]     = f2tf(s[nt][2]);
            Ps[(r0 + 8) * PSTR + colp + 1] = f2tf(s[nt][3]);
        }
        __syncwarp();

        // ---- O += P @ V ----
#pragma unroll
        for (int ksx = 0; ksx < 8; ksx++) {
            const int kb = ksx * 8;
            uint32_t a[4];
            ldsm4(a, p_lane + (uint32_t)(kb * 4));
#pragma unroll
            for (int p = 0; p < 8; p++) {
                uint32_t r[4];
                ldsm4(r, vst_u + (uint32_t)(((p * 16 + lb_r) * VSTR + kb + lb_c) * 4));
                mma_tf32(o[2 * p], a, r);
                mma_tf32(o[2 * p + 1], a, r + 2);
            }
        }
        __syncthreads();     // all K/V reads done before next overwrite
    }
#undef ISSUE_KV

    // ---- finalize + write ctx (tf32-rounded for proj GEMM) ----
    float il0 = 1.f / l0, il1 = 1.f / l1;
    int b = bh >> 4, h = bh & 15;
    float* out0 = ctx + (size_t)(b * S_ + g0) * H_ + h * HD_;
    float* out1 = ctx + (size_t)(b * S_ + g1) * H_ + h * HD_;
#pragma unroll
    for (int nt = 0; nt < 16; nt++) {
        int col = nt * 8 + 2 * lc;
        float2 v0 = { f2tff(o[nt][0] * il0), f2tff(o[nt][1] * il0) };
        float2 v1 = { f2tff(o[nt][2] * il1), f2tff(o[nt][3] * il1) };
        *(float2*)(out0 + col) = v0;
        *(float2*)(out1 + col) = v1;
    }
}

// ---------------- launch ----------------
extern "C" void kernel_launch(void* const* d_in, const int* in_sizes, int n_in,
                              void* d_out, int out_size)
{
    const float* hidden = (const float*)d_in[0];
    const float* cosb   = (const float*)d_in[1];
    const float* sinb   = (const float*)d_in[2];
    // d_in[3]: attention_mask (pure causal -> implemented directly)
    const float* logn   = (const float*)d_in[4];
    const float* Wc     = (const float*)d_in[5];
    const float* bc     = (const float*)d_in[6];
    const float* Wp     = (const float*)d_in[7];
    const float* bp     = (const float*)d_in[8];
    float* out = (float*)d_out;

    float *qkv, *Q, *Kt, *Vt, *ctx, *hid_tf, *wct, *wpt;
    cudaGetSymbolAddress((void**)&qkv,    g_qkv);
    cudaGetSymbolAddress((void**)&Q,      g_q);
    cudaGetSymbolAddress((void**)&Kt,     g_k);
    cudaGetSymbolAddress((void**)&Vt,     g_v);
    cudaGetSymbolAddress((void**)&ctx,    g_ctx);
    cudaGetSymbolAddress((void**)&hid_tf, g_hid_tf);
    cudaGetSymbolAddress((void**)&wct,    g_wct);
    cudaGetSymbolAddress((void**)&wpt,    g_wpt);

    cudaFuncSetAttribute(gemm_tf32,
                         cudaFuncAttributeMaxDynamicSharedMemorySize, GEMM_SMEM);
    cudaFuncSetAttribute(flash_tc,
                         cudaFuncAttributeMaxDynamicSharedMemorySize, FLASH_SMEM);

    // 0) pre-round A; transpose+round weights to [N][K]
    {
        int n4h = (ROWS_ * H_) / 4;
        to_tf32k<<<(n4h + 255) / 256, 256>>>(hidden, hid_tf, n4h);
        wtrans<<<dim3(H_ / 32, QKV_N / 32), dim3(32, 8)>>>(Wc, wct, H_, QKV_N);
        wtrans<<<dim3(H_ / 32, H_ / 32), dim3(32, 8)>>>(Wp, wpt, H_, H_);
    }

    // 1) qkv = hidden @ Wc + bc   [4096,6144]
    gemm_tf32<<<dim3(QKV_N / 128, ROWS_ / 128), 256, GEMM_SMEM>>>(
        hid_tf, wct, bc, qkv, ROWS_, QKV_N, H_);

    // 2) rope + logn -> Q,K [b,h,s,d];  V transpose -> [b,h,d,s]
    {
        int total = B_ * S_ * NH_ * HD_;
        rope_split<<<(total + 255) / 256, 256>>>(qkv, cosb, sinb, logn, Q, Kt);
        vtrans<<<dim3(S_ / 32, HD_ / 32, B_ * NH_), dim3(32, 8)>>>(qkv, Vt);
    }

    // 3) flash attention -> ctx [4096, 2048]
    flash_tc<<<dim3(S_ / FBQ, B_ * NH_), 256, FLASH_SMEM>>>(Q, Kt, Vt, ctx);

    // 4) out = ctx @ Wp + bp      [4096,2048]
    gemm_tf32<<<dim3(H_ / 128, ROWS_ / 128), 256, GEMM_SMEM>>>(
        ctx, wpt, bp, out, ROWS_, H_, H_);
}

// round 11
// speedup vs baseline: 1.1810x; 1.0830x over previous
#include <cuda_runtime.h>
#include <cuda_bf16.h>
#include <math.h>
#include <stdint.h>

// Problem constants
#define B_  2
#define S_  2048
#define H_  2048
#define NH_ 16
#define HD_ 128
#define ROWS_ (B_ * S_)        // 4096
#define QKV_N (3 * H_)         // 6144

// ---------------- scratch (static device globals; no allocation) ----------------
__device__ float g_q[(size_t)B_ * NH_ * S_ * HD_];        // [b,h,s,d] tf32-rounded
__device__ float g_k[(size_t)B_ * NH_ * S_ * HD_];        // [b,h,s,d] tf32-rounded
__device__ float g_v[(size_t)B_ * NH_ * S_ * HD_];        // [b,h,d,s] tf32-rounded
__device__ float g_ctx[(size_t)ROWS_ * H_];               // [b*s, h*d] tf32-rounded
__device__ float g_hid_tf[(size_t)ROWS_ * H_];            // tf32-rounded A
__device__ float g_wct[(size_t)QKV_N * H_];               // Wc^T [6144][2048] tf32
__device__ float g_wpt[(size_t)H_ * H_];                  // Wp^T [2048][2048] tf32

// ---------------- helpers ----------------
__device__ __forceinline__ uint32_t f2tf(float x) {
    uint32_t r;
    asm("cvt.rna.tf32.f32 %0, %1;" : "=r"(r) : "f"(x));
    return r;
}
__device__ __forceinline__ float f2tff(float x) { return __uint_as_float(f2tf(x)); }

__device__ __forceinline__ void mma_tf32(float* c, const uint32_t* a, const uint32_t* b) {
    asm volatile(
        "mma.sync.aligned.m16n8k8.row.col.f32.tf32.tf32.f32 "
        "{%0,%1,%2,%3}, {%4,%5,%6,%7}, {%8,%9}, {%0,%1,%2,%3};\n"
        : "+f"(c[0]), "+f"(c[1]), "+f"(c[2]), "+f"(c[3])
        : "r"(a[0]), "r"(a[1]), "r"(a[2]), "r"(a[3]),
          "r"(b[0]), "r"(b[1]));
}
__device__ __forceinline__ void ldsm4(uint32_t* r, uint32_t addr) {
    asm volatile("ldmatrix.sync.aligned.m8n8.x4.shared.b16 {%0,%1,%2,%3}, [%4];"
        : "=r"(r[0]), "=r"(r[1]), "=r"(r[2]), "=r"(r[3]) : "r"(addr));
}
__device__ __forceinline__ uint32_t smem_u32(const void* p) {
    return (uint32_t)__cvta_generic_to_shared(p);
}
__device__ __forceinline__ void cp16(uint32_t dst, const void* src) {
    asm volatile("cp.async.cg.shared.global [%0], [%1], 16;" :: "r"(dst), "l"(src));
}
__device__ __forceinline__ void cp_commit() {
    asm volatile("cp.async.commit_group;");
}
template<int N> __device__ __forceinline__ void cp_wait() {
    asm volatile("cp.async.wait_group %0;" :: "n"(N));
}

// ---------------- merged preprocessing: round hidden, transpose+round Wc/Wp ----------------
__device__ __forceinline__ void wtrans_body(
    const float* __restrict__ in, float* __restrict__ out,
    int K, int N, int k0, int n0, int tid, float (*t)[33])
{
    const int x = tid & 31, y = tid >> 5;    // 32 x 8
#pragma unroll
    for (int i = 0; i < 32; i += 8)
        t[y + i][x] = in[(size_t)(k0 + y + i) * N + n0 + x];
    __syncthreads();
#pragma unroll
    for (int i = 0; i < 32; i += 8)
        out[(size_t)(n0 + y + i) * K + k0 + x] = f2tff(t[x][y + i]);
}

#define PREP_H 8192     // hidden float4 blocks
#define PREP_WC 12288   // Wc trans blocks (64 x 192)
#define PREP_WP 4096    // Wp trans blocks (64 x 64)

__global__ __launch_bounds__(256) void prep_all(
    const float* __restrict__ hidden, const float* __restrict__ Wc,
    const float* __restrict__ Wp,
    float* __restrict__ hid_tf, float* __restrict__ wct, float* __restrict__ wpt)
{
    __shared__ float t[32][33];
    const int bid = blockIdx.x;
    if (bid < PREP_H) {
        int i = bid * 256 + threadIdx.x;
        float4 v = ((const float4*)hidden)[i];
        v.x = f2tff(v.x); v.y = f2tff(v.y); v.z = f2tff(v.z); v.w = f2tff(v.w);
        ((float4*)hid_tf)[i] = v;
    } else if (bid < PREP_H + PREP_WC) {
        int id = bid - PREP_H;
        wtrans_body(Wc, wct, H_, QKV_N, (id & 63) * 32, (id >> 6) * 32, threadIdx.x, t);
    } else {
        int id = bid - PREP_H - PREP_WC;
        wtrans_body(Wp, wpt, H_, H_, (id & 63) * 32, (id >> 6) * 32, threadIdx.x, t);
    }
}

// ---------------- TF32 GEMM mainloop config (R7): 128x128, BK=32, 3 stages ----------------
#define GSTR 36
#define GT_ST (128 * GSTR)
#define G_ST  (2 * GT_ST)
#define GEMM_SMEM (3 * G_ST * 4)    // 110592 B
#define TSSTR 132                    // epilogue staging tile stride (float4-aligned)

#define GEMM_MAINLOOP(Aptr, Bptr)                                                 \
    const uint32_t as_u = smem_u32(gsm);                                          \
    const int tid = threadIdx.x;                                                  \
    const int bx = blockIdx.x, by = blockIdx.y;                                   \
    const int warp = tid >> 5, lane = tid & 31;                                   \
    const int wm = (warp & 1) * 64;                                               \
    const int wn = (warp >> 1) * 32;                                              \
    const int lr = lane >> 2;                                                     \
    const int lc = lane & 3;                                                      \
    const int la_m = lane & 15;                                                   \
    const int la_k = (lane >> 4) << 2;                                            \
    const int lb_r = (lane & 7) + ((lane >> 4) << 3);                             \
    const int lb_c = ((lane >> 3) & 1) << 2;                                      \
    const uint32_t a_lane = as_u + (uint32_t)(((wm + la_m) * GSTR + la_k) * 4);   \
    const uint32_t b_lane = as_u + (uint32_t)(GT_ST * 4)                          \
                          + (uint32_t)(((wn + lb_r) * GSTR + lb_c) * 4);          \
    const float* Ab = (Aptr) + (size_t)(by * 128) * K;                            \
    const float* Bb = (Bptr) + (size_t)(bx * 128) * K;                            \
    const int KT = K >> 5;                                                        \
    ISSUE_TILE(0, 0); cp_commit();                                                \
    ISSUE_TILE(1, 1); cp_commit();                                                \
    float c[4][4][4];                                                             \
    _Pragma("unroll")                                                             \
    for (int mt = 0; mt < 4; mt++)                                                \
        _Pragma("unroll")                                                         \
        for (int nt = 0; nt < 4; nt++)                                            \
            _Pragma("unroll")                                                     \
            for (int j = 0; j < 4; j++) c[mt][nt][j] = 0.f;                       \
    for (int kt = 0; kt < KT; kt++) {                                             \
        cp_wait<1>();                                                             \
        __syncthreads();                                                          \
        if (kt + 2 < KT) { ISSUE_TILE(kt + 2, (kt + 2) % 3); }                    \
        cp_commit();                                                              \
        const uint32_t stoff = (uint32_t)((kt % 3) * G_ST * 4);                   \
        const uint32_t a_st = a_lane + stoff;                                     \
        const uint32_t b_st = b_lane + stoff;                                     \
        _Pragma("unroll")                                                         \
        for (int ks = 0; ks < 4; ks++) {                                          \
            const int kb = ks * 8;                                                \
            uint32_t af[4][4], bf[4][2];                                          \
            _Pragma("unroll")                                                     \
            for (int mt = 0; mt < 4; mt++)                                        \
                ldsm4(af[mt], a_st + (uint32_t)((mt * 16 * GSTR + kb) * 4));      \
            _Pragma("unroll")                                                     \
            for (int p = 0; p < 2; p++) {                                         \
                uint32_t r[4];                                                    \
                ldsm4(r, b_st + (uint32_t)((p * 16 * GSTR + kb) * 4));            \
                bf[2 * p][0] = r[0]; bf[2 * p][1] = r[1];                         \
                bf[2 * p + 1][0] = r[2]; bf[2 * p + 1][1] = r[3];                 \
            }                                                                     \
            _Pragma("unroll")                                                     \
            for (int mt = 0; mt < 4; mt++)                                        \
                _Pragma("unroll")                                                 \
                for (int nt = 0; nt < 4; nt++)                                    \
                    mma_tf32(c[mt][nt], af[mt], bf[nt]);                          \
        }                                                                         \
    }

#define ISSUE_TILE(kt, st)                                                        \
    do {                                                                          \
        const float* Asrc = Ab + (kt) * 32;                                       \
        const float* Bsrc = Bb + (kt) * 32;                                       \
        uint32_t au = as_u + (uint32_t)((st) * G_ST * 4);                         \
        uint32_t bu = au + (uint32_t)(GT_ST * 4);                                 \
        _Pragma("unroll")                                                         \
        for (int i = 0; i < 4; i++) {                                             \
            int ch = tid + 256 * i;                                               \
            int r = ch >> 3, c2 = (ch & 7) << 2;                                  \
            cp16(au + (uint32_t)((r * GSTR + c2) * 4), Asrc + (size_t)r * K + c2);\
            cp16(bu + (uint32_t)((r * GSTR + c2) * 4), Bsrc + (size_t)r * K + c2);\
        }                                                                         \
    } while (0)

// ---------------- plain GEMM (proj): C = A @ Bt^T + bias ----------------
__global__ __launch_bounds__(256, 2) void gemm_tf32(
    const float* __restrict__ A, const float* __restrict__ Bt,
    const float* __restrict__ bias, float* __restrict__ C,
    int M, int N, int K)
{
    extern __shared__ float gsm[];
    GEMM_MAINLOOP(A, Bt)

#pragma unroll
    for (int mt = 0; mt < 4; mt++) {
        int row = by * 128 + wm + mt * 16 + lr;
#pragma unroll
        for (int nt = 0; nt < 4; nt++) {
            int col = bx * 128 + wn + nt * 8 + 2 * lc;
            float b0 = bias[col], b1 = bias[col + 1];
            float2 v0 = { c[mt][nt][0] + b0, c[mt][nt][1] + b1 };
            float2 v1 = { c[mt][nt][2] + b0, c[mt][nt][3] + b1 };
            *(float2*)(C + (size_t)row * N + col) = v0;
            *(float2*)(C + (size_t)(row + 8) * N + col) = v1;
        }
    }
}

// ---------------- fused QKV GEMM: rope+logn for Q/K tiles, transpose for V tiles ----------------
// bx 0..15 -> Q head bx; 16..31 -> K head bx-16; 32..47 -> V head bx-32.
__global__ __launch_bounds__(256, 2) void gemm_qkv(
    const float* __restrict__ A, const float* __restrict__ Bt,
    const float* __restrict__ bias,
    const float* __restrict__ cosb, const float* __restrict__ sinb,
    const float* __restrict__ logn,
    float* __restrict__ Qo, float* __restrict__ Ko, float* __restrict__ Vo,
    int M, int N, int K)
{
    extern __shared__ float gsm[];
    GEMM_MAINLOOP(A, Bt)

    __syncthreads();                 // mainloop smem reads done; reuse as staging
    float* ts = gsm;                 // [128][TSSTR]
    const bool isV = (bx >= 32);

    // store tile (+bias) to smem; V tiles stored transposed [d][s]
#pragma unroll
    for (int mt = 0; mt < 4; mt++) {
        int row = wm + mt * 16 + lr;
#pragma unroll
        for (int nt = 0; nt < 4; nt++) {
            int col = wn + nt * 8 + 2 * lc;
            float b0 = bias[bx * 128 + col], b1 = bias[bx * 128 + col + 1];
            float v00 = c[mt][nt][0] + b0, v01 = c[mt][nt][1] + b1;
            float v10 = c[mt][nt][2] + b0, v11 = c[mt][nt][3] + b1;
            if (!isV) {
                ts[row * TSSTR + col] = v00;
                ts[row * TSSTR + col + 1] = v01;
                ts[(row + 8) * TSSTR + col] = v10;
                ts[(row + 8) * TSSTR + col + 1] = v11;
            } else {
                ts[col * TSSTR + row] = v00;
                ts[(col + 1) * TSSTR + row] = v01;
                ts[col * TSSTR + row + 8] = v10;
                ts[(col + 1) * TSSTR + row + 8] = v11;
            }
        }
    }
    __syncthreads();

    if (!isV) {
        const bool isQ = (bx < 16);
        const int h = bx & 15;
        float* dst = isQ ? Qo : Ko;
        for (int t = tid; t < 128 * 32; t += 256) {
            int r = t >> 5, c4 = (t & 31) << 2;
            int sg = by * 128 + r;
            int b = sg >> 11;
            int s = sg & (S_ - 1);           // within-batch position (FIX)
            const float* rowp = ts + r * TSSTR;
            float4 v  = *(const float4*)(rowp + c4);
            int dro = (c4 < 64) ? (c4 + 64) : (c4 - 64);
            float4 vo = *(const float4*)(rowp + dro);
            float4 cv = *(const float4*)(cosb + (size_t)s * HD_ + c4);
            float4 sv = *(const float4*)(sinb + (size_t)s * HD_ + c4);
            float sgn = (c4 < 64) ? -1.f : 1.f;
            float4 res;
            res.x = v.x * cv.x + sgn * vo.x * sv.x;
            res.y = v.y * cv.y + sgn * vo.y * sv.y;
            res.z = v.z * cv.z + sgn * vo.z * sv.z;
            res.w = v.w * cv.w + sgn * vo.w * sv.w;
            if (isQ) {
                float ln = logn[s] * 0.08838834764831845f;
                res.x *= ln; res.y *= ln; res.z *= ln; res.w *= ln;
            }
            size_t oidx = (((size_t)(b * NH_ + h) * S_ + s) << 7) + c4;
            uint4 u = { f2tf(res.x), f2tf(res.y), f2tf(res.z), f2tf(res.w) };
            *(uint4*)(dst + oidx) = u;
        }
    } else {
        const int h = bx - 32;
        const int b = by >> 4;
        const int sl0 = (by & 15) * 128;   // local s base within batch
        for (int t = tid; t < 128 * 32; t += 256) {
            int d = t >> 5, s4 = (t & 31) << 2;
            float4 v = *(const float4*)(ts + d * TSSTR + s4);
            uint4 u = { f2tf(v.x), f2tf(v.y), f2tf(v.z), f2tf(v.w) };
            size_t oidx = ((size_t)((b * NH_ + h) * HD_ + d) * S_) + sl0 + s4;
            *(uint4*)(Vo + oidx) = u;
        }
    }
}

// ---------------- Flash attention v3: Q regs, K+V dbuf, PV warp tile m64n32 ----------------
#define FBQ 128
#define FBKT 64
#define KSTR 132
#define VSTR 68
#define PSTR 68
#define FK_ST (FBKT * KSTR)            // 8448 words per K stage
#define FV_ST (HD_ * VSTR)             // 8704 words per V stage
#define OFF_V (2 * FK_ST)              // 16896
#define OFF_P (OFF_V + 2 * FV_ST)      // 34304
#define OFF_AL (OFF_P + FBQ * PSTR)    // 43008
#define FLASH_SMEM ((OFF_AL + 2 * FBQ) * 4)   // 173056 B

__global__ __launch_bounds__(256) void flash_tc(
    const float* __restrict__ Q, const float* __restrict__ K,
    const float* __restrict__ V, float* __restrict__ ctx)
{
    extern __shared__ float fsm[];
    uint32_t* Ps = (uint32_t*)(fsm + OFF_P);
    float* al_s = fsm + OFF_AL;          // [128]
    float* l_s  = al_s + FBQ;            // [128]
    const uint32_t ks_u = smem_u32(fsm);
    const uint32_t vs_u = ks_u + (uint32_t)(OFF_V * 4);
    const uint32_t ps_u = smem_u32(Ps);

    const int qt = (S_ / FBQ - 1) - blockIdx.x;   // heavy tiles first
    const int bh = blockIdx.y;
    const int tid = threadIdx.x;
    const int warp = tid >> 5, lane = tid & 31;
    const int lr = lane >> 2;
    const int lc = lane & 3;

    const int la_m = lane & 15;
    const int la_k = (lane >> 4) << 2;
    const int lb_r = (lane & 7) + ((lane >> 4) << 3);
    const int lb_c = ((lane >> 3) & 1) << 2;

    // PV warp tile: m64 x n32 (2m x 4n)
    const int wm2 = (warp & 1) * 64;
    const int wn2 = (warp >> 1) * 32;
    const uint32_t p_lane = ps_u + (uint32_t)(((wm2 + la_m) * PSTR + la_k) * 4);

    const float* Qb = Q + ((size_t)bh * S_ + qt * FBQ) * HD_;
    const float* Kb = K + (size_t)bh * S_ * HD_;
    const float* Vb = V + (size_t)bh * HD_ * S_;   // [d][s]

    // ---- stage Q through K-region smem once; ldmatrix into registers ----
    for (int t = tid; t < FBQ * (HD_ / 4); t += 256) {
        int r = t >> 5, c4 = (t & 31) << 2;
        *(uint4*)(fsm + r * KSTR + c4) = *(const uint4*)(Qb + (size_t)r * HD_ + c4);
    }
    __syncthreads();
    uint32_t qf[16][4];
    {
        const uint32_t q_lane = ks_u + (uint32_t)(((warp * 16 + la_m) * KSTR + la_k) * 4);
#pragma unroll
        for (int ks = 0; ks < 16; ks++)
            ldsm4(qf[ks], q_lane + (uint32_t)(ks * 8 * 4));
    }
    __syncthreads();

    const int nkt = 2 * qt + 2;

#define ISSUE_KV(kt)                                                              \
    do {                                                                          \
        const float* ksrc = Kb + (size_t)(kt) * FBKT * HD_;                       \
        const float* vsrc = Vb + (size_t)(kt) * FBKT;                             \
        uint32_t kdst = ks_u + (uint32_t)(((kt) & 1) * FK_ST * 4);                \
        uint32_t vdst = vs_u + (uint32_t)(((kt) & 1) * FV_ST * 4);                \
        _Pragma("unroll")                                                         \
        for (int i = 0; i < 8; i++) {                                             \
            int ch = tid + 256 * i;                                               \
            int kr = ch >> 5, kc = (ch & 31) << 2;                                \
            cp16(kdst + (uint32_t)((kr * KSTR + kc) * 4),                         \
                 ksrc + (size_t)kr * HD_ + kc);                                   \
            int vr = ch >> 4, vc = (ch & 15) << 2;                                \
            cp16(vdst + (uint32_t)((vr * VSTR + vc) * 4),                         \
                 vsrc + (size_t)vr * S_ + vc);                                    \
        }                                                                         \
    } while (0)

    ISSUE_KV(0);
    cp_commit();

    float m0 = -1e30f, m1 = -1e30f;
    float l0 = 0.f, l1 = 0.f;
    float o[4][4][4];
#pragma unroll
    for (int mt = 0; mt < 4; mt++)
#pragma unroll
        for (int nt = 0; nt < 4; nt++)
#pragma unroll
            for (int j = 0; j < 4; j++) o[mt][nt][j] = 0.f;

    const int r0 = warp * 16 + lr;        // QK/softmax row ownership
    const int g0 = qt * FBQ + r0;
    const int g1 = g0 + 8;

    for (int kt = 0; kt < nkt; kt++) {
        if (kt + 1 < nkt) {
            ISSUE_KV(kt + 1);
            cp_commit();
            cp_wait<1>();
        } else {
            cp_wait<0>();
        }
        __syncthreads();                   // KV(kt) visible

        const uint32_t kst_u = ks_u + (uint32_t)((kt & 1) * FK_ST * 4);
        const uint32_t vst_u = vs_u + (uint32_t)((kt & 1) * FV_ST * 4);

        // ---- S = Q @ K^T (m16 x n64 per warp) ----
        float s[8][4];
#pragma unroll
        for (int nt = 0; nt < 8; nt++)
#pragma unroll
            for (int j = 0; j < 4; j++) s[nt][j] = 0.f;

#pragma unroll
        for (int ksx = 0; ksx < 16; ksx++) {
            const int kb = ksx * 8;
#pragma unroll
            for (int p = 0; p < 4; p++) {
                uint32_t r[4];
                ldsm4(r, kst_u + (uint32_t)(((p * 16 + lb_r) * KSTR + kb + lb_c) * 4));
                mma_tf32(s[2 * p], qf[ksx], r);
                mma_tf32(s[2 * p + 1], qf[ksx], r + 2);
            }
        }

        // ---- causal mask ----
        if (kt * FBKT + FBKT - 1 > qt * FBQ + warp * 16) {
#pragma unroll
            for (int nt = 0; nt < 8; nt++) {
                int colb = kt * FBKT + nt * 8 + 2 * lc;
                if (colb > g0)     s[nt][0] = -1e30f;
                if (colb + 1 > g0) s[nt][1] = -1e30f;
                if (colb > g1)     s[nt][2] = -1e30f;
                if (colb + 1 > g1) s[nt][3] = -1e30f;
            }
        }

        // ---- online softmax (rows owned by QK warp) ----
        float mx0 = -1e30f, mx1 = -1e30f;
#pragma unroll
        for (int nt = 0; nt < 8; nt++) {
            mx0 = fmaxf(mx0, fmaxf(s[nt][0], s[nt][1]));
            mx1 = fmaxf(mx1, fmaxf(s[nt][2], s[nt][3]));
        }
        mx0 = fmaxf(mx0, __shfl_xor_sync(0xffffffffu, mx0, 1));
        mx0 = fmaxf(mx0, __shfl_xor_sync(0xffffffffu, mx0, 2));
        mx1 = fmaxf(mx1, __shfl_xor_sync(0xffffffffu, mx1, 1));
        mx1 = fmaxf(mx1, __shfl_xor_sync(0xffffffffu, mx1, 2));

        float nm0 = fmaxf(m0, mx0), nm1 = fmaxf(m1, mx1);
        float al0 = __expf(m0 - nm0), al1 = __expf(m1 - nm1);
        m0 = nm0; m1 = nm1;

        float sum0 = 0.f, sum1 = 0.f;
#pragma unroll
        for (int nt = 0; nt < 8; nt++) {
            s[nt][0] = __expf(s[nt][0] - nm0);
            s[nt][1] = __expf(s[nt][1] - nm0);
            s[nt][2] = __expf(s[nt][2] - nm1);
            s[nt][3] = __expf(s[nt][3] - nm1);
            sum0 += s[nt][0] + s[nt][1];
            sum1 += s[nt][2] + s[nt][3];
        }
        sum0 += __shfl_xor_sync(0xffffffffu, sum0, 1);
        sum0 += __shfl_xor_sync(0xffffffffu, sum0, 2);
        sum1 += __shfl_xor_sync(0xffffffffu, sum1, 1);
        sum1 += __shfl_xor_sync(0xffffffffu, sum1, 2);
        l0 = l0 * al0 + sum0;
        l1 = l1 * al1 + sum1;

        if (lc == 0) {
            al_s[r0] = al0;
            al_s[r0 + 8] = al1;
        }

        // ---- store P (tf32) ----
#pragma unroll
        for (int nt = 0; nt < 8; nt++) {
            int colp = nt * 8 + 2 * lc;
            Ps[r0 * PSTR + colp]           = f2tf(s[nt][0]);
            Ps[r0 * PSTR + colp + 1]       = f2tf(s[nt][1]);
            Ps[(r0 + 8) * PSTR + colp]     = f2tf(s[nt][2]);
            Ps[(r0 + 8) * PSTR + colp + 1] = f2tf(s[nt][3]);
        }
        __syncthreads();                   // publish P + al

        // ---- O rescale + O += P @ V  (m64 x n32 per warp) ----
#pragma unroll
        for (int mt = 0; mt < 4; mt++) {
            float a0 = al_s[wm2 + mt * 16 + lr];
            float a1 = al_s[wm2 + mt * 16 + lr + 8];
#pragma unroll
            for (int nt = 0; nt < 4; nt++) {
                o[mt][nt][0] *= a0; o[mt][nt][1] *= a0;
                o[mt][nt][2] *= a1; o[mt][nt][3] *= a1;
            }
        }
#pragma unroll
        for (int ksx = 0; ksx < 8; ksx++) {
            const int kb = ksx * 8;
            uint32_t af[4][4], bf[4][2];
#pragma unroll
            for (int mt = 0; mt < 4; mt++)
                ldsm4(af[mt], p_lane + (uint32_t)((mt * 16 * PSTR + kb) * 4));
#pragma unroll
            for (int p = 0; p < 2; p++) {
                uint32_t r[4];
                ldsm4(r, vst_u + (uint32_t)(((wn2 + p * 16 + lb_r) * VSTR + kb + lb_c) * 4));
                bf[2 * p][0] = r[0]; bf[2 * p][1] = r[1];
                bf[2 * p + 1][0] = r[2]; bf[2 * p + 1][1] = r[3];
            }
#pragma unroll
            for (int mt = 0; mt < 4; mt++)
#pragma unroll
                for (int nt = 0; nt < 4; nt++)
                    mma_tf32(o[mt][nt], af[mt], bf[nt]);
        }
        __syncthreads();                   // all reads done before overwrite
    }
#undef ISSUE_KV

    // ---- publish final l, then write O (PV layout) ----
    if (lc == 0) {
        l_s[r0] = l0;
        l_s[r0 + 8] = l1;
    }
    __syncthreads();

    const int b = bh >> 4, h = bh & 15;
#pragma unroll
    for (int mt = 0; mt < 4; mt++) {
        int rloc = wm2 + mt * 16 + lr;
        int row0 = qt * FBQ + rloc;
        float il0 = 1.f / l_s[rloc];
        float il1 = 1.f / l_s[rloc + 8];
        float* out0 = ctx + (size_t)(b * S_ + row0) * H_ + h * HD_ + wn2;
        float* out1 = out0 + (size_t)8 * H_;
#pragma unroll
        for (int nt = 0; nt < 4; nt++) {
            int col = nt * 8 + 2 * lc;
            float2 v0 = { f2tff(o[mt][nt][0] * il0), f2tff(o[mt][nt][1] * il0) };
            float2 v1 = { f2tff(o[mt][nt][2] * il1), f2tff(o[mt][nt][3] * il1) };
            *(float2*)(out0 + col) = v0;
            *(float2*)(out1 + col) = v1;
        }
    }
}

// ---------------- launch ----------------
extern "C" void kernel_launch(void* const* d_in, const int* in_sizes, int n_in,
                              void* d_out, int out_size)
{
    const float* hidden = (const float*)d_in[0];
    const float* cosb   = (const float*)d_in[1];
    const float* sinb   = (const float*)d_in[2];
    // d_in[3]: attention_mask (pure causal -> implemented directly)
    const float* logn   = (const float*)d_in[4];
    const float* Wc     = (const float*)d_in[5];
    const float* bc     = (const float*)d_in[6];
    const float* Wp     = (const float*)d_in[7];
    const float* bp     = (const float*)d_in[8];
    float* out = (float*)d_out;

    float *Q, *Kt, *Vt, *ctx, *hid_tf, *wct, *wpt;
    cudaGetSymbolAddress((void**)&Q,      g_q);
    cudaGetSymbolAddress((void**)&Kt,     g_k);
    cudaGetSymbolAddress((void**)&Vt,     g_v);
    cudaGetSymbolAddress((void**)&ctx,    g_ctx);
    cudaGetSymbolAddress((void**)&hid_tf, g_hid_tf);
    cudaGetSymbolAddress((void**)&wct,    g_wct);
    cudaGetSymbolAddress((void**)&wpt,    g_wpt);

    cudaFuncSetAttribute(gemm_tf32,
                         cudaFuncAttributeMaxDynamicSharedMemorySize, GEMM_SMEM);
    cudaFuncSetAttribute(gemm_qkv,
                         cudaFuncAttributeMaxDynamicSharedMemorySize, GEMM_SMEM);
    cudaFuncSetAttribute(flash_tc,
                         cudaFuncAttributeMaxDynamicSharedMemorySize, FLASH_SMEM);

    // 0) pre-round A + transpose/round weights (one launch)
    prep_all<<<PREP_H + PREP_WC + PREP_WP, 256>>>(hidden, Wc, Wp, hid_tf, wct, wpt);

    // 1) fused QKV GEMM + rope/logn/V-transpose -> g_q, g_k, g_v
    gemm_qkv<<<dim3(QKV_N / 128, ROWS_ / 128), 256, GEMM_SMEM>>>(
        hid_tf, wct, bc, cosb, sinb, logn, Q, Kt, Vt, ROWS_, QKV_N, H_);

    // 2) flash attention -> ctx [4096, 2048]
    flash_tc<<<dim3(S_ / FBQ, B_ * NH_), 256, FLASH_SMEM>>>(Q, Kt, Vt, ctx);

    // 3) out = ctx @ Wp + bp      [4096,2048]
    gemm_tf32<<<dim3(H_ / 128, ROWS_ / 128), 256, GEMM_SMEM>>>(
        ctx, wpt, bp, out, ROWS_, H_, H_);
}

// round 12
// speedup vs baseline: 1.1878x; 1.0058x over previous
#include <cuda_runtime.h>
#include <cuda_bf16.h>
#include <math.h>
#include <stdint.h>

// Problem constants
#define B_  2
#define S_  2048
#define H_  2048
#define NH_ 16
#define HD_ 128
#define ROWS_ (B_ * S_)        // 4096
#define QKV_N (3 * H_)         // 6144

// ---------------- scratch (static device globals; no allocation) ----------------
__device__ float g_q[(size_t)B_ * NH_ * S_ * HD_];        // [b,h,s,d] tf32-rounded (log2e folded)
__device__ float g_k[(size_t)B_ * NH_ * S_ * HD_];        // [b,h,s,d] tf32-rounded
__device__ float g_v[(size_t)B_ * NH_ * S_ * HD_];        // [b,h,d,s] tf32-rounded
__device__ float g_ctx[(size_t)ROWS_ * H_];               // [b*s, h*d] tf32-rounded
__device__ float g_hid_tf[(size_t)ROWS_ * H_];            // tf32-rounded A
__device__ float g_wct[(size_t)QKV_N * H_];               // Wc^T [6144][2048] tf32
__device__ float g_wpt[(size_t)H_ * H_];                  // Wp^T [2048][2048] tf32

// ---------------- helpers ----------------
__device__ __forceinline__ uint32_t f2tf(float x) {
    uint32_t r;
    asm("cvt.rna.tf32.f32 %0, %1;" : "=r"(r) : "f"(x));
    return r;
}
__device__ __forceinline__ float f2tff(float x) { return __uint_as_float(f2tf(x)); }

__device__ __forceinline__ void mma_tf32(float* c, const uint32_t* a, const uint32_t* b) {
    asm volatile(
        "mma.sync.aligned.m16n8k8.row.col.f32.tf32.tf32.f32 "
        "{%0,%1,%2,%3}, {%4,%5,%6,%7}, {%8,%9}, {%0,%1,%2,%3};\n"
        : "+f"(c[0]), "+f"(c[1]), "+f"(c[2]), "+f"(c[3])
        : "r"(a[0]), "r"(a[1]), "r"(a[2]), "r"(a[3]),
          "r"(b[0]), "r"(b[1]));
}
__device__ __forceinline__ void ldsm4(uint32_t* r, uint32_t addr) {
    asm volatile("ldmatrix.sync.aligned.m8n8.x4.shared.b16 {%0,%1,%2,%3}, [%4];"
        : "=r"(r[0]), "=r"(r[1]), "=r"(r[2]), "=r"(r[3]) : "r"(addr));
}
__device__ __forceinline__ uint32_t smem_u32(const void* p) {
    return (uint32_t)__cvta_generic_to_shared(p);
}
__device__ __forceinline__ void cp16(uint32_t dst, const void* src) {
    asm volatile("cp.async.cg.shared.global [%0], [%1], 16;" :: "r"(dst), "l"(src));
}
__device__ __forceinline__ void cp_commit() {
    asm volatile("cp.async.commit_group;");
}
template<int N> __device__ __forceinline__ void cp_wait() {
    asm volatile("cp.async.wait_group %0;" :: "n"(N));
}

// ---------------- merged preprocessing: round hidden, transpose+round Wc/Wp ----------------
__device__ __forceinline__ void wtrans_body(
    const float* __restrict__ in, float* __restrict__ out,
    int K, int N, int k0, int n0, int tid, float (*t)[33])
{
    const int x = tid & 31, y = tid >> 5;    // 32 x 8
#pragma unroll
    for (int i = 0; i < 32; i += 8)
        t[y + i][x] = in[(size_t)(k0 + y + i) * N + n0 + x];
    __syncthreads();
#pragma unroll
    for (int i = 0; i < 32; i += 8)
        out[(size_t)(n0 + y + i) * K + k0 + x] = f2tff(t[x][y + i]);
}

#define PREP_H 8192     // hidden float4 blocks
#define PREP_WC 12288   // Wc trans blocks (64 x 192)
#define PREP_WP 4096    // Wp trans blocks (64 x 64)

__global__ __launch_bounds__(256) void prep_all(
    const float* __restrict__ hidden, const float* __restrict__ Wc,
    const float* __restrict__ Wp,
    float* __restrict__ hid_tf, float* __restrict__ wct, float* __restrict__ wpt)
{
    __shared__ float t[32][33];
    const int bid = blockIdx.x;
    if (bid < PREP_H) {
        int i = bid * 256 + threadIdx.x;
        float4 v = ((const float4*)hidden)[i];
        v.x = f2tff(v.x); v.y = f2tff(v.y); v.z = f2tff(v.z); v.w = f2tff(v.w);
        ((float4*)hid_tf)[i] = v;
    } else if (bid < PREP_H + PREP_WC) {
        int id = bid - PREP_H;
        wtrans_body(Wc, wct, H_, QKV_N, (id & 63) * 32, (id >> 6) * 32, threadIdx.x, t);
    } else {
        int id = bid - PREP_H - PREP_WC;
        wtrans_body(Wp, wpt, H_, H_, (id & 63) * 32, (id >> 6) * 32, threadIdx.x, t);
    }
}

// ---------------- TF32 GEMM mainloop config (R7): 128x128, BK=32, 3 stages ----------------
#define GSTR 36
#define GT_ST (128 * GSTR)
#define G_ST  (2 * GT_ST)
#define GEMM_SMEM (3 * G_ST * 4)    // 110592 B
#define TSSTR 132                    // epilogue staging tile stride (float4-aligned)

#define GEMM_MAINLOOP(Aptr, Bptr)                                                 \
    const uint32_t as_u = smem_u32(gsm);                                          \
    const int tid = threadIdx.x;                                                  \
    const int bx = blockIdx.x, by = blockIdx.y;                                   \
    const int warp = tid >> 5, lane = tid & 31;                                   \
    const int wm = (warp & 1) * 64;                                               \
    const int wn = (warp >> 1) * 32;                                              \
    const int lr = lane >> 2;                                                     \
    const int lc = lane & 3;                                                      \
    const int la_m = lane & 15;                                                   \
    const int la_k = (lane >> 4) << 2;                                            \
    const int lb_r = (lane & 7) + ((lane >> 4) << 3);                             \
    const int lb_c = ((lane >> 3) & 1) << 2;                                      \
    const uint32_t a_lane = as_u + (uint32_t)(((wm + la_m) * GSTR + la_k) * 4);   \
    const uint32_t b_lane = as_u + (uint32_t)(GT_ST * 4)                          \
                          + (uint32_t)(((wn + lb_r) * GSTR + lb_c) * 4);          \
    const float* Ab = (Aptr) + (size_t)(by * 128) * K;                            \
    const float* Bb = (Bptr) + (size_t)(bx * 128) * K;                            \
    const int KT = K >> 5;                                                        \
    ISSUE_TILE(0, 0); cp_commit();                                                \
    ISSUE_TILE(1, 1); cp_commit();                                                \
    float c[4][4][4];                                                             \
    _Pragma("unroll")                                                             \
    for (int mt = 0; mt < 4; mt++)                                                \
        _Pragma("unroll")                                                         \
        for (int nt = 0; nt < 4; nt++)                                            \
            _Pragma("unroll")                                                     \
            for (int j = 0; j < 4; j++) c[mt][nt][j] = 0.f;                       \
    for (int kt = 0; kt < KT; kt++) {                                             \
        cp_wait<1>();                                                             \
        __syncthreads();                                                          \
        if (kt + 2 < KT) { ISSUE_TILE(kt + 2, (kt + 2) % 3); }                    \
        cp_commit();                                                              \
        const uint32_t stoff = (uint32_t)((kt % 3) * G_ST * 4);                   \
        const uint32_t a_st = a_lane + stoff;                                     \
        const uint32_t b_st = b_lane + stoff;                                     \
        _Pragma("unroll")                                                         \
        for (int ks = 0; ks < 4; ks++) {                                          \
            const int kb = ks * 8;                                                \
            uint32_t af[4][4], bf[4][2];                                          \
            _Pragma("unroll")                                                     \
            for (int mt = 0; mt < 4; mt++)                                        \
                ldsm4(af[mt], a_st + (uint32_t)((mt * 16 * GSTR + kb) * 4));      \
            _Pragma("unroll")                                                     \
            for (int p = 0; p < 2; p++) {                                         \
                uint32_t r[4];                                                    \
                ldsm4(r, b_st + (uint32_t)((p * 16 * GSTR + kb) * 4));            \
                bf[2 * p][0] = r[0]; bf[2 * p][1] = r[1];                         \
                bf[2 * p + 1][0] = r[2]; bf[2 * p + 1][1] = r[3];                 \
            }                                                                     \
            _Pragma("unroll")                                                     \
            for (int mt = 0; mt < 4; mt++)                                        \
                _Pragma("unroll")                                                 \
                for (int nt = 0; nt < 4; nt++)                                    \
                    mma_tf32(c[mt][nt], af[mt], bf[nt]);                          \
        }                                                                         \
    }

#define ISSUE_TILE(kt, st)                                                        \
    do {                                                                          \
        const float* Asrc = Ab + (kt) * 32;                                       \
        const float* Bsrc = Bb + (kt) * 32;                                       \
        uint32_t au = as_u + (uint32_t)((st) * G_ST * 4);                         \
        uint32_t bu = au + (uint32_t)(GT_ST * 4);                                 \
        _Pragma("unroll")                                                         \
        for (int i = 0; i < 4; i++) {                                             \
            int ch = tid + 256 * i;                                               \
            int r = ch >> 3, c2 = (ch & 7) << 2;                                  \
            cp16(au + (uint32_t)((r * GSTR + c2) * 4), Asrc + (size_t)r * K + c2);\
            cp16(bu + (uint32_t)((r * GSTR + c2) * 4), Bsrc + (size_t)r * K + c2);\
        }                                                                         \
    } while (0)

// ---------------- plain GEMM (proj): C = A @ Bt^T + bias ----------------
__global__ __launch_bounds__(256, 2) void gemm_tf32(
    const float* __restrict__ A, const float* __restrict__ Bt,
    const float* __restrict__ bias, float* __restrict__ C,
    int M, int N, int K)
{
    extern __shared__ float gsm[];
    GEMM_MAINLOOP(A, Bt)

#pragma unroll
    for (int mt = 0; mt < 4; mt++) {
        int row = by * 128 + wm + mt * 16 + lr;
#pragma unroll
        for (int nt = 0; nt < 4; nt++) {
            int col = bx * 128 + wn + nt * 8 + 2 * lc;
            float b0 = bias[col], b1 = bias[col + 1];
            float2 v0 = { c[mt][nt][0] + b0, c[mt][nt][1] + b1 };
            float2 v1 = { c[mt][nt][2] + b0, c[mt][nt][3] + b1 };
            *(float2*)(C + (size_t)row * N + col) = v0;
            *(float2*)(C + (size_t)(row + 8) * N + col) = v1;
        }
    }
}

// ---------------- fused QKV GEMM: rope+logn for Q/K tiles, transpose for V tiles ----------------
// bx 0..15 -> Q head bx; 16..31 -> K head bx-16; 32..47 -> V head bx-32.
__global__ __launch_bounds__(256, 2) void gemm_qkv(
    const float* __restrict__ A, const float* __restrict__ Bt,
    const float* __restrict__ bias,
    const float* __restrict__ cosb, const float* __restrict__ sinb,
    const float* __restrict__ logn,
    float* __restrict__ Qo, float* __restrict__ Ko, float* __restrict__ Vo,
    int M, int N, int K)
{
    extern __shared__ float gsm[];
    GEMM_MAINLOOP(A, Bt)

    __syncthreads();                 // mainloop smem reads done; reuse as staging
    float* ts = gsm;                 // [128][TSSTR]
    const bool isV = (bx >= 32);

    // store tile (+bias) to smem; V tiles stored transposed [d][s]
#pragma unroll
    for (int mt = 0; mt < 4; mt++) {
        int row = wm + mt * 16 + lr;
#pragma unroll
        for (int nt = 0; nt < 4; nt++) {
            int col = wn + nt * 8 + 2 * lc;
            float b0 = bias[bx * 128 + col], b1 = bias[bx * 128 + col + 1];
            float v00 = c[mt][nt][0] + b0, v01 = c[mt][nt][1] + b1;
            float v10 = c[mt][nt][2] + b0, v11 = c[mt][nt][3] + b1;
            if (!isV) {
                ts[row * TSSTR + col] = v00;
                ts[row * TSSTR + col + 1] = v01;
                ts[(row + 8) * TSSTR + col] = v10;
                ts[(row + 8) * TSSTR + col + 1] = v11;
            } else {
                ts[col * TSSTR + row] = v00;
                ts[(col + 1) * TSSTR + row] = v01;
                ts[col * TSSTR + row + 8] = v10;
                ts[(col + 1) * TSSTR + row + 8] = v11;
            }
        }
    }
    __syncthreads();

    if (!isV) {
        const bool isQ = (bx < 16);
        const int h = bx & 15;
        float* dst = isQ ? Qo : Ko;
        for (int t = tid; t < 128 * 32; t += 256) {
            int r = t >> 5, c4 = (t & 31) << 2;
            int sg = by * 128 + r;
            int b = sg >> 11;
            int s = sg & (S_ - 1);           // within-batch position
            const float* rowp = ts + r * TSSTR;
            float4 v  = *(const float4*)(rowp + c4);
            int dro = (c4 < 64) ? (c4 + 64) : (c4 - 64);
            float4 vo = *(const float4*)(rowp + dro);
            float4 cv = *(const float4*)(cosb + (size_t)s * HD_ + c4);
            float4 sv = *(const float4*)(sinb + (size_t)s * HD_ + c4);
            float sgn = (c4 < 64) ? -1.f : 1.f;
            float4 res;
            res.x = v.x * cv.x + sgn * vo.x * sv.x;
            res.y = v.y * cv.y + sgn * vo.y * sv.y;
            res.z = v.z * cv.z + sgn * vo.z * sv.z;
            res.w = v.w * cv.w + sgn * vo.w * sv.w;
            if (isQ) {
                // fold 1/sqrt(HD) * logn * log2(e)  (softmax done in exp2 domain)
                float ln = logn[s] * 0.08838834764831845f * 1.4426950408889634f;
                res.x *= ln; res.y *= ln; res.z *= ln; res.w *= ln;
            }
            size_t oidx = (((size_t)(b * NH_ + h) * S_ + s) << 7) + c4;
            uint4 u = { f2tf(res.x), f2tf(res.y), f2tf(res.z), f2tf(res.w) };
            *(uint4*)(dst + oidx) = u;
        }
    } else {
        const int h = bx - 32;
        const int b = by >> 4;
        const int sl0 = (by & 15) * 128;   // local s base within batch
        for (int t = tid; t < 128 * 32; t += 256) {
            int d = t >> 5, s4 = (t & 31) << 2;
            float4 v = *(const float4*)(ts + d * TSSTR + s4);
            uint4 u = { f2tf(v.x), f2tf(v.y), f2tf(v.z), f2tf(v.w) };
            size_t oidx = ((size_t)((b * NH_ + h) * HD_ + d) * S_) + sl0 + s4;
            *(uint4*)(Vo + oidx) = u;
        }
    }
}

// ---------------- Flash attention v4: frag pipelines, exp2 softmax ----------------
#define FBQ 128
#define FBKT 64
#define KSTR 132
#define VSTR 68
#define PSTR 68
#define FK_ST (FBKT * KSTR)            // 8448 words per K stage
#define FV_ST (HD_ * VSTR)             // 8704 words per V stage
#define OFF_V (2 * FK_ST)              // 16896
#define OFF_P (OFF_V + 2 * FV_ST)      // 34304
#define OFF_AL (OFF_P + FBQ * PSTR)    // 43008
#define FLASH_SMEM ((OFF_AL + 2 * FBQ) * 4)   // 173056 B

__global__ __launch_bounds__(256) void flash_tc(
    const float* __restrict__ Q, const float* __restrict__ K,
    const float* __restrict__ V, float* __restrict__ ctx)
{
    extern __shared__ float fsm[];
    uint32_t* Ps = (uint32_t*)(fsm + OFF_P);
    float* al_s = fsm + OFF_AL;          // [128]
    float* l_s  = al_s + FBQ;            // [128]
    const uint32_t ks_u = smem_u32(fsm);
    const uint32_t vs_u = ks_u + (uint32_t)(OFF_V * 4);
    const uint32_t ps_u = smem_u32(Ps);

    const int qt = (S_ / FBQ - 1) - blockIdx.x;   // heavy tiles first
    const int bh = blockIdx.y;
    const int tid = threadIdx.x;
    const int warp = tid >> 5, lane = tid & 31;
    const int lr = lane >> 2;
    const int lc = lane & 3;

    const int la_m = lane & 15;
    const int la_k = (lane >> 4) << 2;
    const int lb_r = (lane & 7) + ((lane >> 4) << 3);
    const int lb_c = ((lane >> 3) & 1) << 2;

    // PV warp tile: m64 x n32 (2m x 4n)
    const int wm2 = (warp & 1) * 64;
    const int wn2 = (warp >> 1) * 32;
    const uint32_t p_lane = ps_u + (uint32_t)(((wm2 + la_m) * PSTR + la_k) * 4);

    const float* Qb = Q + ((size_t)bh * S_ + qt * FBQ) * HD_;
    const float* Kb = K + (size_t)bh * S_ * HD_;
    const float* Vb = V + (size_t)bh * HD_ * S_;   // [d][s]

    // ---- stage Q through K-region smem once; ldmatrix into registers ----
    for (int t = tid; t < FBQ * (HD_ / 4); t += 256) {
        int r = t >> 5, c4 = (t & 31) << 2;
        *(uint4*)(fsm + r * KSTR + c4) = *(const uint4*)(Qb + (size_t)r * HD_ + c4);
    }
    __syncthreads();
    uint32_t qf[16][4];
    {
        const uint32_t q_lane = ks_u + (uint32_t)(((warp * 16 + la_m) * KSTR + la_k) * 4);
#pragma unroll
        for (int ks = 0; ks < 16; ks++)
            ldsm4(qf[ks], q_lane + (uint32_t)(ks * 8 * 4));
    }
    __syncthreads();

    const int nkt = 2 * qt + 2;

#define ISSUE_KV(kt)                                                              \
    do {                                                                          \
        const float* ksrc = Kb + (size_t)(kt) * FBKT * HD_;                       \
        const float* vsrc = Vb + (size_t)(kt) * FBKT;                             \
        uint32_t kdst = ks_u + (uint32_t)(((kt) & 1) * FK_ST * 4);                \
        uint32_t vdst = vs_u + (uint32_t)(((kt) & 1) * FV_ST * 4);                \
        _Pragma("unroll")                                                         \
        for (int i = 0; i < 8; i++) {                                             \
            int ch = tid + 256 * i;                                               \
            int kr = ch >> 5, kc = (ch & 31) << 2;                                \
            cp16(kdst + (uint32_t)((kr * KSTR + kc) * 4),                         \
                 ksrc + (size_t)kr * HD_ + kc);                                   \
            int vr = ch >> 4, vc = (ch & 15) << 2;                                \
            cp16(vdst + (uint32_t)((vr * VSTR + vc) * 4),                         \
                 vsrc + (size_t)vr * S_ + vc);                                    \
        }                                                                         \
    } while (0)

    ISSUE_KV(0);
    cp_commit();

    float m0 = -1e30f, m1 = -1e30f;
    float l0 = 0.f, l1 = 0.f;
    float o[4][4][4];
#pragma unroll
    for (int mt = 0; mt < 4; mt++)
#pragma unroll
        for (int nt = 0; nt < 4; nt++)
#pragma unroll
            for (int j = 0; j < 4; j++) o[mt][nt][j] = 0.f;

    const int r0 = warp * 16 + lr;        // QK/softmax row ownership
    const int g0 = qt * FBQ + r0;
    const int g1 = g0 + 8;

    for (int kt = 0; kt < nkt; kt++) {
        if (kt + 1 < nkt) {
            ISSUE_KV(kt + 1);
            cp_commit();
            cp_wait<1>();
        } else {
            cp_wait<0>();
        }
        __syncthreads();                   // KV(kt) visible

        const uint32_t kst_u = ks_u + (uint32_t)((kt & 1) * FK_ST * 4);
        const uint32_t vst_u = vs_u + (uint32_t)((kt & 1) * FV_ST * 4);
        const uint32_t k_lane = kst_u + (uint32_t)((lb_r * KSTR + lb_c) * 4);

        // ---- S = Q @ K^T (m16 x n64 per warp), K-frag double buffer ----
        float s[8][4];
#pragma unroll
        for (int nt = 0; nt < 8; nt++)
#pragma unroll
            for (int j = 0; j < 4; j++) s[nt][j] = 0.f;

        uint32_t kf[2][4][4];
#pragma unroll
        for (int p = 0; p < 4; p++)
            ldsm4(kf[0][p], k_lane + (uint32_t)((p * 16 * KSTR) * 4));
#pragma unroll
        for (int ksx = 0; ksx < 16; ksx++) {
            const int cur = ksx & 1;
            if (ksx < 15) {
                const int kbn = (ksx + 1) * 8;
#pragma unroll
                for (int p = 0; p < 4; p++)
                    ldsm4(kf[cur ^ 1][p], k_lane + (uint32_t)((p * 16 * KSTR + kbn) * 4));
            }
#pragma unroll
            for (int p = 0; p < 4; p++) {
                mma_tf32(s[2 * p], qf[ksx], kf[cur][p]);
                mma_tf32(s[2 * p + 1], qf[ksx], kf[cur][p] + 2);
            }
        }

        // ---- causal mask ----
        if (kt * FBKT + FBKT - 1 > qt * FBQ + warp * 16) {
#pragma unroll
            for (int nt = 0; nt < 8; nt++) {
                int colb = kt * FBKT + nt * 8 + 2 * lc;
                if (colb > g0)     s[nt][0] = -1e30f;
                if (colb + 1 > g0) s[nt][1] = -1e30f;
                if (colb > g1)     s[nt][2] = -1e30f;
                if (colb + 1 > g1) s[nt][3] = -1e30f;
            }
        }

        // ---- online softmax in exp2 domain (log2e pre-folded into Q scale) ----
        float mx0 = -1e30f, mx1 = -1e30f;
#pragma unroll
        for (int nt = 0; nt < 8; nt++) {
            mx0 = fmaxf(mx0, fmaxf(s[nt][0], s[nt][1]));
            mx1 = fmaxf(mx1, fmaxf(s[nt][2], s[nt][3]));
        }
        mx0 = fmaxf(mx0, __shfl_xor_sync(0xffffffffu, mx0, 1));
        mx0 = fmaxf(mx0, __shfl_xor_sync(0xffffffffu, mx0, 2));
        mx1 = fmaxf(mx1, __shfl_xor_sync(0xffffffffu, mx1, 1));
        mx1 = fmaxf(mx1, __shfl_xor_sync(0xffffffffu, mx1, 2));

        float nm0 = fmaxf(m0, mx0), nm1 = fmaxf(m1, mx1);
        float al0 = exp2f(m0 - nm0), al1 = exp2f(m1 - nm1);
        m0 = nm0; m1 = nm1;

        float sum0 = 0.f, sum1 = 0.f;
#pragma unroll
        for (int nt = 0; nt < 8; nt++) {
            s[nt][0] = exp2f(s[nt][0] - nm0);
            s[nt][1] = exp2f(s[nt][1] - nm0);
            s[nt][2] = exp2f(s[nt][2] - nm1);
            s[nt][3] = exp2f(s[nt][3] - nm1);
            sum0 += s[nt][0] + s[nt][1];
            sum1 += s[nt][2] + s[nt][3];
        }
        sum0 += __shfl_xor_sync(0xffffffffu, sum0, 1);
        sum0 += __shfl_xor_sync(0xffffffffu, sum0, 2);
        sum1 += __shfl_xor_sync(0xffffffffu, sum1, 1);
        sum1 += __shfl_xor_sync(0xffffffffu, sum1, 2);
        l0 = l0 * al0 + sum0;
        l1 = l1 * al1 + sum1;

        if (lc == 0) {
            al_s[r0] = al0;
            al_s[r0 + 8] = al1;
        }

        // ---- store P (tf32) ----
#pragma unroll
        for (int nt = 0; nt < 8; nt++) {
            int colp = nt * 8 + 2 * lc;
            Ps[r0 * PSTR + colp]           = f2tf(s[nt][0]);
            Ps[r0 * PSTR + colp + 1]       = f2tf(s[nt][1]);
            Ps[(r0 + 8) * PSTR + colp]     = f2tf(s[nt][2]);
            Ps[(r0 + 8) * PSTR + colp + 1] = f2tf(s[nt][3]);
        }
        __syncthreads();                   // publish P + al

        // ---- O rescale ----
#pragma unroll
        for (int mt = 0; mt < 4; mt++) {
            float a0 = al_s[wm2 + mt * 16 + lr];
            float a1 = al_s[wm2 + mt * 16 + lr + 8];
#pragma unroll
            for (int nt = 0; nt < 4; nt++) {
                o[mt][nt][0] *= a0; o[mt][nt][1] *= a0;
                o[mt][nt][2] *= a1; o[mt][nt][3] *= a1;
            }
        }

        // ---- O += P @ V (m64 x n32 per warp), frag double buffer ----
        const uint32_t v_lane = vst_u + (uint32_t)(((wn2 + lb_r) * VSTR + lb_c) * 4);
        uint32_t pa[2][4][4], pb[2][2][4];
#pragma unroll
        for (int mt = 0; mt < 4; mt++)
            ldsm4(pa[0][mt], p_lane + (uint32_t)((mt * 16 * PSTR) * 4));
#pragma unroll
        for (int p = 0; p < 2; p++)
            ldsm4(pb[0][p], v_lane + (uint32_t)((p * 16 * VSTR) * 4));

#pragma unroll
        for (int ksx = 0; ksx < 8; ksx++) {
            const int cur = ksx & 1;
            if (ksx < 7) {
                const int kbn = (ksx + 1) * 8;
#pragma unroll
                for (int mt = 0; mt < 4; mt++)
                    ldsm4(pa[cur ^ 1][mt], p_lane + (uint32_t)((mt * 16 * PSTR + kbn) * 4));
#pragma unroll
                for (int p = 0; p < 2; p++)
                    ldsm4(pb[cur ^ 1][p], v_lane + (uint32_t)((p * 16 * VSTR + kbn) * 4));
            }
#pragma unroll
            for (int mt = 0; mt < 4; mt++) {
                mma_tf32(o[mt][0], pa[cur][mt], pb[cur][0]);
                mma_tf32(o[mt][1], pa[cur][mt], pb[cur][0] + 2);
                mma_tf32(o[mt][2], pa[cur][mt], pb[cur][1]);
                mma_tf32(o[mt][3], pa[cur][mt], pb[cur][1] + 2);
            }
        }
        __syncthreads();                   // all reads done before overwrite
    }
#undef ISSUE_KV

    // ---- publish final l, then write O (PV layout) ----
    if (lc == 0) {
        l_s[r0] = l0;
        l_s[r0 + 8] = l1;
    }
    __syncthreads();

    const int b = bh >> 4, h = bh & 15;
#pragma unroll
    for (int mt = 0; mt < 4; mt++) {
        int rloc = wm2 + mt * 16 + lr;
        int row0 = qt * FBQ + rloc;
        float il0 = 1.f / l_s[rloc];
        float il1 = 1.f / l_s[rloc + 8];
        float* out0 = ctx + (size_t)(b * S_ + row0) * H_ + h * HD_ + wn2;
        float* out1 = out0 + (size_t)8 * H_;
#pragma unroll
        for (int nt = 0; nt < 4; nt++) {
            int col = nt * 8 + 2 * lc;
            float2 v0 = { f2tff(o[mt][nt][0] * il0), f2tff(o[mt][nt][1] * il0) };
            float2 v1 = { f2tff(o[mt][nt][2] * il1), f2tff(o[mt][nt][3] * il1) };
            *(float2*)(out0 + col) = v0;
            *(float2*)(out1 + col) = v1;
        }
    }
}

// ---------------- launch ----------------
extern "C" void kernel_launch(void* const* d_in, const int* in_sizes, int n_in,
                              void* d_out, int out_size)
{
    const float* hidden = (const float*)d_in[0];
    const float* cosb   = (const float*)d_in[1];
    const float* sinb   = (const float*)d_in[2];
    // d_in[3]: attention_mask (pure causal -> implemented directly)
    const float* logn   = (const float*)d_in[4];
    const float* Wc     = (const float*)d_in[5];
    const float* bc     = (const float*)d_in[6];
    const float* Wp     = (const float*)d_in[7];
    const float* bp     = (const float*)d_in[8];
    float* out = (float*)d_out;

    float *Q, *Kt, *Vt, *ctx, *hid_tf, *wct, *wpt;
    cudaGetSymbolAddress((void**)&Q,      g_q);
    cudaGetSymbolAddress((void**)&Kt,     g_k);
    cudaGetSymbolAddress((void**)&Vt,     g_v);
    cudaGetSymbolAddress((void**)&ctx,    g_ctx);
    cudaGetSymbolAddress((void**)&hid_tf, g_hid_tf);
    cudaGetSymbolAddress((void**)&wct,    g_wct);
    cudaGetSymbolAddress((void**)&wpt,    g_wpt);

    cudaFuncSetAttribute(gemm_tf32,
                         cudaFuncAttributeMaxDynamicSharedMemorySize, GEMM_SMEM);
    cudaFuncSetAttribute(gemm_qkv,
                         cudaFuncAttributeMaxDynamicSharedMemorySize, GEMM_SMEM);
    cudaFuncSetAttribute(flash_tc,
                         cudaFuncAttributeMaxDynamicSharedMemorySize, FLASH_SMEM);

    // 0) pre-round A + transpose/round weights (one launch)
    prep_all<<<PREP_H + PREP_WC + PREP_WP, 256>>>(hidden, Wc, Wp, hid_tf, wct, wpt);

    // 1) fused QKV GEMM + rope/logn/V-transpose -> g_q, g_k, g_v
    gemm_qkv<<<dim3(QKV_N / 128, ROWS_ / 128), 256, GEMM_SMEM>>>(
        hid_tf, wct, bc, cosb, sinb, logn, Q, Kt, Vt, ROWS_, QKV_N, H_);

    // 2) flash attention -> ctx [4096, 2048]
    flash_tc<<<dim3(S_ / FBQ, B_ * NH_), 256, FLASH_SMEM>>>(Q, Kt, Vt, ctx);

    // 3) out = ctx @ Wp + bp      [4096,2048]
    gemm_tf32<<<dim3(H_ / 128, ROWS_ / 128), 256, GEMM_SMEM>>>(
        ctx, wpt, bp, out, ROWS_, H_, H_);
}

// round 13
// speedup vs baseline: 1.2804x; 1.0780x over previous
#include <cuda_runtime.h>
#include <cuda_bf16.h>
#include <math.h>
#include <stdint.h>

// Problem constants
#define B_  2
#define S_  2048
#define H_  2048
#define NH_ 16
#define HD_ 128
#define ROWS_ (B_ * S_)        // 4096
#define QKV_N (3 * H_)         // 6144

// ---------------- scratch (static device globals; no allocation) ----------------
__device__ float g_q[(size_t)B_ * NH_ * S_ * HD_];        // [b,h,s,d] tf32-rounded (log2e folded)
__device__ float g_k[(size_t)B_ * NH_ * S_ * HD_];        // [b,h,s,d] tf32-rounded
__device__ float g_v[(size_t)B_ * NH_ * S_ * HD_];        // [b,h,d,s] tf32-rounded
__device__ float g_ctx[(size_t)ROWS_ * H_];               // [b*s, h*d] tf32-rounded
__device__ float g_hid_tf[(size_t)ROWS_ * H_];            // tf32-rounded A
__device__ float g_wct[(size_t)QKV_N * H_];               // Wc^T [6144][2048] tf32
__device__ float g_wpt[(size_t)H_ * H_];                  // Wp^T [2048][2048] tf32

// ---------------- helpers ----------------
__device__ __forceinline__ uint32_t f2tf(float x) {
    uint32_t r;
    asm("cvt.rna.tf32.f32 %0, %1;" : "=r"(r) : "f"(x));
    return r;
}
__device__ __forceinline__ float f2tff(float x) { return __uint_as_float(f2tf(x)); }

__device__ __forceinline__ void mma_tf32(float* c, const uint32_t* a, const uint32_t* b) {
    asm volatile(
        "mma.sync.aligned.m16n8k8.row.col.f32.tf32.tf32.f32 "
        "{%0,%1,%2,%3}, {%4,%5,%6,%7}, {%8,%9}, {%0,%1,%2,%3};\n"
        : "+f"(c[0]), "+f"(c[1]), "+f"(c[2]), "+f"(c[3])
        : "r"(a[0]), "r"(a[1]), "r"(a[2]), "r"(a[3]),
          "r"(b[0]), "r"(b[1]));
}
__device__ __forceinline__ void ldsm4(uint32_t* r, uint32_t addr) {
    asm volatile("ldmatrix.sync.aligned.m8n8.x4.shared.b16 {%0,%1,%2,%3}, [%4];"
        : "=r"(r[0]), "=r"(r[1]), "=r"(r[2]), "=r"(r[3]) : "r"(addr));
}
__device__ __forceinline__ uint32_t smem_u32(const void* p) {
    return (uint32_t)__cvta_generic_to_shared(p);
}
__device__ __forceinline__ void cp16(uint32_t dst, const void* src) {
    asm volatile("cp.async.cg.shared.global [%0], [%1], 16;" :: "r"(dst), "l"(src));
}
__device__ __forceinline__ void cp_commit() {
    asm volatile("cp.async.commit_group;");
}
template<int N> __device__ __forceinline__ void cp_wait() {
    asm volatile("cp.async.wait_group %0;" :: "n"(N));
}

// ---------------- merged preprocessing (float4 transposes) ----------------
// 32x32 tile transpose+round: load float4 rows, store float4 along K.
__device__ __forceinline__ void wtrans_body4(
    const float* __restrict__ in, float* __restrict__ out,
    int K, int N, int k0, int n0, int tid, float (*t)[33])
{
    const int x4 = tid & 7, y = tid >> 3;    // 8 float4-cols x 32 rows
    {
        float4 v = *(const float4*)(in + (size_t)(k0 + y) * N + n0 + x4 * 4);
        t[y][x4 * 4 + 0] = v.x;
        t[y][x4 * 4 + 1] = v.y;
        t[y][x4 * 4 + 2] = v.z;
        t[y][x4 * 4 + 3] = v.w;
    }
    __syncthreads();
    {
        // out[(n0+y)*K + k0 + x4*4 + i] = t[x4*4+i][y]
        float4 v;
        v.x = f2tff(t[x4 * 4 + 0][y]);
        v.y = f2tff(t[x4 * 4 + 1][y]);
        v.z = f2tff(t[x4 * 4 + 2][y]);
        v.w = f2tff(t[x4 * 4 + 3][y]);
        *(float4*)(out + (size_t)(n0 + y) * K + k0 + x4 * 4) = v;
    }
}

#define PREP_H 8192     // hidden float4 blocks
#define PREP_WC 12288   // Wc trans blocks (64 x 192)
#define PREP_WP 4096    // Wp trans blocks (64 x 64)

__global__ __launch_bounds__(256) void prep_all(
    const float* __restrict__ hidden, const float* __restrict__ Wc,
    const float* __restrict__ Wp,
    float* __restrict__ hid_tf, float* __restrict__ wct, float* __restrict__ wpt)
{
    __shared__ float t[32][33];
    const int bid = blockIdx.x;
    if (bid < PREP_H) {
        int i = bid * 256 + threadIdx.x;
        float4 v = ((const float4*)hidden)[i];
        v.x = f2tff(v.x); v.y = f2tff(v.y); v.z = f2tff(v.z); v.w = f2tff(v.w);
        ((float4*)hid_tf)[i] = v;
    } else if (bid < PREP_H + PREP_WC) {
        int id = bid - PREP_H;
        wtrans_body4(Wc, wct, H_, QKV_N, (id & 63) * 32, (id >> 6) * 32, threadIdx.x, t);
    } else {
        int id = bid - PREP_H - PREP_WC;
        wtrans_body4(Wp, wpt, H_, H_, (id & 63) * 32, (id >> 6) * 32, threadIdx.x, t);
    }
}

// ---------------- TF32 GEMM mainloop config: 128x128, BK=32, 3 stages ----------------
#define GSTR 36
#define GT_ST (128 * GSTR)
#define G_ST  (2 * GT_ST)
#define GEMM_SMEM (3 * G_ST * 4)    // 110592 B
#define TSSTR 132                    // epilogue staging tile stride

// Issue of next tile moved after the first k8 sub-chunk (spreads LSU burst).
#define GEMM_MAINLOOP(Aptr, Bptr)                                                 \
    const uint32_t as_u = smem_u32(gsm);                                          \
    const int tid = threadIdx.x;                                                  \
    const int bx = blockIdx.x, by = blockIdx.y;                                   \
    const int warp = tid >> 5, lane = tid & 31;                                   \
    const int wm = (warp & 1) * 64;                                               \
    const int wn = (warp >> 1) * 32;                                              \
    const int lr = lane >> 2;                                                     \
    const int lc = lane & 3;                                                      \
    const int la_m = lane & 15;                                                   \
    const int la_k = (lane >> 4) << 2;                                            \
    const int lb_r = (lane & 7) + ((lane >> 4) << 3);                             \
    const int lb_c = ((lane >> 3) & 1) << 2;                                      \
    const uint32_t a_lane = as_u + (uint32_t)(((wm + la_m) * GSTR + la_k) * 4);   \
    const uint32_t b_lane = as_u + (uint32_t)(GT_ST * 4)                          \
                          + (uint32_t)(((wn + lb_r) * GSTR + lb_c) * 4);          \
    const float* Ab = (Aptr) + (size_t)(by * 128) * K;                            \
    const float* Bb = (Bptr) + (size_t)(bx * 128) * K;                            \
    const int KT = K >> 5;                                                        \
    ISSUE_TILE(0, 0); cp_commit();                                                \
    ISSUE_TILE(1, 1); cp_commit();                                                \
    float c[4][4][4];                                                             \
    _Pragma("unroll")                                                             \
    for (int mt = 0; mt < 4; mt++)                                                \
        _Pragma("unroll")                                                         \
        for (int nt = 0; nt < 4; nt++)                                            \
            _Pragma("unroll")                                                     \
            for (int j = 0; j < 4; j++) c[mt][nt][j] = 0.f;                       \
    for (int kt = 0; kt < KT; kt++) {                                             \
        cp_wait<1>();                                                             \
        __syncthreads();                                                          \
        const uint32_t stoff = (uint32_t)((kt % 3) * G_ST * 4);                   \
        const uint32_t a_st = a_lane + stoff;                                     \
        const uint32_t b_st = b_lane + stoff;                                     \
        _Pragma("unroll")                                                         \
        for (int ks = 0; ks < 4; ks++) {                                          \
            const int kb = ks * 8;                                                \
            uint32_t af[4][4], bf[4][2];                                          \
            _Pragma("unroll")                                                     \
            for (int mt = 0; mt < 4; mt++)                                        \
                ldsm4(af[mt], a_st + (uint32_t)((mt * 16 * GSTR + kb) * 4));      \
            _Pragma("unroll")                                                     \
            for (int p = 0; p < 2; p++) {                                         \
                uint32_t r[4];                                                    \
                ldsm4(r, b_st + (uint32_t)((p * 16 * GSTR + kb) * 4));            \
                bf[2 * p][0] = r[0]; bf[2 * p][1] = r[1];                         \
                bf[2 * p + 1][0] = r[2]; bf[2 * p + 1][1] = r[3];                 \
            }                                                                     \
            _Pragma("unroll")                                                     \
            for (int mt = 0; mt < 4; mt++)                                        \
                _Pragma("unroll")                                                 \
                for (int nt = 0; nt < 4; nt++)                                    \
                    mma_tf32(c[mt][nt], af[mt], bf[nt]);                          \
            if (ks == 0) {                                                        \
                if (kt + 2 < KT) { ISSUE_TILE(kt + 2, (kt + 2) % 3); }            \
                cp_commit();                                                      \
            }                                                                     \
        }                                                                         \
    }

#define ISSUE_TILE(kt, st)                                                        \
    do {                                                                          \
        const float* Asrc = Ab + (kt) * 32;                                       \
        const float* Bsrc = Bb + (kt) * 32;                                       \
        uint32_t au = as_u + (uint32_t)((st) * G_ST * 4);                         \
        uint32_t bu = au + (uint32_t)(GT_ST * 4);                                 \
        _Pragma("unroll")                                                         \
        for (int i = 0; i < 4; i++) {                                             \
            int ch = tid + 256 * i;                                               \
            int r = ch >> 3, c2 = (ch & 7) << 2;                                  \
            cp16(au + (uint32_t)((r * GSTR + c2) * 4), Asrc + (size_t)r * K + c2);\
            cp16(bu + (uint32_t)((r * GSTR + c2) * 4), Bsrc + (size_t)r * K + c2);\
        }                                                                         \
    } while (0)

// ---------------- plain GEMM (proj): C = A @ Bt^T + bias ----------------
__global__ __launch_bounds__(256, 2) void gemm_tf32(
    const float* __restrict__ A, const float* __restrict__ Bt,
    const float* __restrict__ bias, float* __restrict__ C,
    int M, int N, int K)
{
    extern __shared__ float gsm[];
    GEMM_MAINLOOP(A, Bt)

#pragma unroll
    for (int mt = 0; mt < 4; mt++) {
        int row = by * 128 + wm + mt * 16 + lr;
#pragma unroll
        for (int nt = 0; nt < 4; nt++) {
            int col = bx * 128 + wn + nt * 8 + 2 * lc;
            float b0 = bias[col], b1 = bias[col + 1];
            float2 v0 = { c[mt][nt][0] + b0, c[mt][nt][1] + b1 };
            float2 v1 = { c[mt][nt][2] + b0, c[mt][nt][3] + b1 };
            *(float2*)(C + (size_t)row * N + col) = v0;
            *(float2*)(C + (size_t)(row + 8) * N + col) = v1;
        }
    }
}

// ---------------- fused QKV GEMM: rope+logn for Q/K tiles, transpose for V tiles ----------------
__global__ __launch_bounds__(256, 2) void gemm_qkv(
    const float* __restrict__ A, const float* __restrict__ Bt,
    const float* __restrict__ bias,
    const float* __restrict__ cosb, const float* __restrict__ sinb,
    const float* __restrict__ logn,
    float* __restrict__ Qo, float* __restrict__ Ko, float* __restrict__ Vo,
    int M, int N, int K)
{
    extern __shared__ float gsm[];
    GEMM_MAINLOOP(A, Bt)

    __syncthreads();                 // mainloop smem reads done; reuse as staging
    float* ts = gsm;                 // [128][TSSTR]
    const bool isV = (bx >= 32);

#pragma unroll
    for (int mt = 0; mt < 4; mt++) {
        int row = wm + mt * 16 + lr;
#pragma unroll
        for (int nt = 0; nt < 4; nt++) {
            int col = wn + nt * 8 + 2 * lc;
            float b0 = bias[bx * 128 + col], b1 = bias[bx * 128 + col + 1];
            float v00 = c[mt][nt][0] + b0, v01 = c[mt][nt][1] + b1;
            float v10 = c[mt][nt][2] + b0, v11 = c[mt][nt][3] + b1;
            if (!isV) {
                ts[row * TSSTR + col] = v00;
                ts[row * TSSTR + col + 1] = v01;
                ts[(row + 8) * TSSTR + col] = v10;
                ts[(row + 8) * TSSTR + col + 1] = v11;
            } else {
                ts[col * TSSTR + row] = v00;
                ts[(col + 1) * TSSTR + row] = v01;
                ts[col * TSSTR + row + 8] = v10;
                ts[(col + 1) * TSSTR + row + 8] = v11;
            }
        }
    }
    __syncthreads();

    if (!isV) {
        const bool isQ = (bx < 16);
        const int h = bx & 15;
        float* dst = isQ ? Qo : Ko;
        for (int t = tid; t < 128 * 32; t += 256) {
            int r = t >> 5, c4 = (t & 31) << 2;
            int sg = by * 128 + r;
            int b = sg >> 11;
            int s = sg & (S_ - 1);           // within-batch position
            const float* rowp = ts + r * TSSTR;
            float4 v  = *(const float4*)(rowp + c4);
            int dro = (c4 < 64) ? (c4 + 64) : (c4 - 64);
            float4 vo = *(const float4*)(rowp + dro);
            float4 cv = *(const float4*)(cosb + (size_t)s * HD_ + c4);
            float4 sv = *(const float4*)(sinb + (size_t)s * HD_ + c4);
            float sgn = (c4 < 64) ? -1.f : 1.f;
            float4 res;
            res.x = v.x * cv.x + sgn * vo.x * sv.x;
            res.y = v.y * cv.y + sgn * vo.y * sv.y;
            res.z = v.z * cv.z + sgn * vo.z * sv.z;
            res.w = v.w * cv.w + sgn * vo.w * sv.w;
            if (isQ) {
                // fold 1/sqrt(HD) * logn * log2(e)  (softmax in exp2 domain)
                float ln = logn[s] * 0.08838834764831845f * 1.4426950408889634f;
                res.x *= ln; res.y *= ln; res.z *= ln; res.w *= ln;
            }
            size_t oidx = (((size_t)(b * NH_ + h) * S_ + s) << 7) + c4;
            uint4 u = { f2tf(res.x), f2tf(res.y), f2tf(res.z), f2tf(res.w) };
            *(uint4*)(dst + oidx) = u;
        }
    } else {
        const int h = bx - 32;
        const int b = by >> 4;
        const int sl0 = (by & 15) * 128;
        for (int t = tid; t < 128 * 32; t += 256) {
            int d = t >> 5, s4 = (t & 31) << 2;
            float4 v = *(const float4*)(ts + d * TSSTR + s4);
            uint4 u = { f2tf(v.x), f2tf(v.y), f2tf(v.z), f2tf(v.w) };
            size_t oidx = ((size_t)((b * NH_ + h) * HD_ + d) * S_) + sl0 + s4;
            *(uint4*)(Vo + oidx) = u;
        }
    }
}

// ---------------- Flash attention v4 (R12 best): frag pipelines, exp2 softmax ----------------
#define FBQ 128
#define FBKT 64
#define KSTR 132
#define VSTR 68
#define PSTR 68
#define FK_ST (FBKT * KSTR)
#define FV_ST (HD_ * VSTR)
#define OFF_V (2 * FK_ST)
#define OFF_P (OFF_V + 2 * FV_ST)
#define OFF_AL (OFF_P + FBQ * PSTR)
#define FLASH_SMEM ((OFF_AL + 2 * FBQ) * 4)   // 173056 B

__global__ __launch_bounds__(256) void flash_tc(
    const float* __restrict__ Q, const float* __restrict__ K,
    const float* __restrict__ V, float* __restrict__ ctx)
{
    extern __shared__ float fsm[];
    uint32_t* Ps = (uint32_t*)(fsm + OFF_P);
    float* al_s = fsm + OFF_AL;
    float* l_s  = al_s + FBQ;
    const uint32_t ks_u = smem_u32(fsm);
    const uint32_t vs_u = ks_u + (uint32_t)(OFF_V * 4);
    const uint32_t ps_u = smem_u32(Ps);

    const int qt = (S_ / FBQ - 1) - blockIdx.x;   // heavy tiles first
    const int bh = blockIdx.y;
    const int tid = threadIdx.x;
    const int warp = tid >> 5, lane = tid & 31;
    const int lr = lane >> 2;
    const int lc = lane & 3;

    const int la_m = lane & 15;
    const int la_k = (lane >> 4) << 2;
    const int lb_r = (lane & 7) + ((lane >> 4) << 3);
    const int lb_c = ((lane >> 3) & 1) << 2;

    const int wm2 = (warp & 1) * 64;
    const int wn2 = (warp >> 1) * 32;
    const uint32_t p_lane = ps_u + (uint32_t)(((wm2 + la_m) * PSTR + la_k) * 4);

    const float* Qb = Q + ((size_t)bh * S_ + qt * FBQ) * HD_;
    const float* Kb = K + (size_t)bh * S_ * HD_;
    const float* Vb = V + (size_t)bh * HD_ * S_;

    for (int t = tid; t < FBQ * (HD_ / 4); t += 256) {
        int r = t >> 5, c4 = (t & 31) << 2;
        *(uint4*)(fsm + r * KSTR + c4) = *(const uint4*)(Qb + (size_t)r * HD_ + c4);
    }
    __syncthreads();
    uint32_t qf[16][4];
    {
        const uint32_t q_lane = ks_u + (uint32_t)(((warp * 16 + la_m) * KSTR + la_k) * 4);
#pragma unroll
        for (int ks = 0; ks < 16; ks++)
            ldsm4(qf[ks], q_lane + (uint32_t)(ks * 8 * 4));
    }
    __syncthreads();

    const int nkt = 2 * qt + 2;

#define ISSUE_KV(kt)                                                              \
    do {                                                                          \
        const float* ksrc = Kb + (size_t)(kt) * FBKT * HD_;                       \
        const float* vsrc = Vb + (size_t)(kt) * FBKT;                             \
        uint32_t kdst = ks_u + (uint32_t)(((kt) & 1) * FK_ST * 4);                \
        uint32_t vdst = vs_u + (uint32_t)(((kt) & 1) * FV_ST * 4);                \
        _Pragma("unroll")                                                         \
        for (int i = 0; i < 8; i++) {                                             \
            int ch = tid + 256 * i;                                               \
            int kr = ch >> 5, kc = (ch & 31) << 2;                                \
            cp16(kdst + (uint32_t)((kr * KSTR + kc) * 4),                         \
                 ksrc + (size_t)kr * HD_ + kc);                                   \
            int vr = ch >> 4, vc = (ch & 15) << 2;                                \
            cp16(vdst + (uint32_t)((vr * VSTR + vc) * 4),                         \
                 vsrc + (size_t)vr * S_ + vc);                                    \
        }                                                                         \
    } while (0)

    ISSUE_KV(0);
    cp_commit();

    float m0 = -1e30f, m1 = -1e30f;
    float l0 = 0.f, l1 = 0.f;
    float o[4][4][4];
#pragma unroll
    for (int mt = 0; mt < 4; mt++)
#pragma unroll
        for (int nt = 0; nt < 4; nt++)
#pragma unroll
            for (int j = 0; j < 4; j++) o[mt][nt][j] = 0.f;

    const int r0 = warp * 16 + lr;
    const int g0 = qt * FBQ + r0;
    const int g1 = g0 + 8;

    for (int kt = 0; kt < nkt; kt++) {
        if (kt + 1 < nkt) {
            ISSUE_KV(kt + 1);
            cp_commit();
            cp_wait<1>();
        } else {
            cp_wait<0>();
        }
        __syncthreads();

        const uint32_t kst_u = ks_u + (uint32_t)((kt & 1) * FK_ST * 4);
        const uint32_t vst_u = vs_u + (uint32_t)((kt & 1) * FV_ST * 4);
        const uint32_t k_lane = kst_u + (uint32_t)((lb_r * KSTR + lb_c) * 4);

        float s[8][4];
#pragma unroll
        for (int nt = 0; nt < 8; nt++)
#pragma unroll
            for (int j = 0; j < 4; j++) s[nt][j] = 0.f;

        uint32_t kf[2][4][4];
#pragma unroll
        for (int p = 0; p < 4; p++)
            ldsm4(kf[0][p], k_lane + (uint32_t)((p * 16 * KSTR) * 4));
#pragma unroll
        for (int ksx = 0; ksx < 16; ksx++) {
            const int cur = ksx & 1;
            if (ksx < 15) {
                const int kbn = (ksx + 1) * 8;
#pragma unroll
                for (int p = 0; p < 4; p++)
                    ldsm4(kf[cur ^ 1][p], k_lane + (uint32_t)((p * 16 * KSTR + kbn) * 4));
            }
#pragma unroll
            for (int p = 0; p < 4; p++) {
                mma_tf32(s[2 * p], qf[ksx], kf[cur][p]);
                mma_tf32(s[2 * p + 1], qf[ksx], kf[cur][p] + 2);
            }
        }

        if (kt * FBKT + FBKT - 1 > qt * FBQ + warp * 16) {
#pragma unroll
            for (int nt = 0; nt < 8; nt++) {
                int colb = kt * FBKT + nt * 8 + 2 * lc;
                if (colb > g0)     s[nt][0] = -1e30f;
                if (colb + 1 > g0) s[nt][1] = -1e30f;
                if (colb > g1)     s[nt][2] = -1e30f;
                if (colb + 1 > g1) s[nt][3] = -1e30f;
            }
        }

        float mx0 = -1e30f, mx1 = -1e30f;
#pragma unroll
        for (int nt = 0; nt < 8; nt++) {
            mx0 = fmaxf(mx0, fmaxf(s[nt][0], s[nt][1]));
            mx1 = fmaxf(mx1, fmaxf(s[nt][2], s[nt][3]));
        }
        mx0 = fmaxf(mx0, __shfl_xor_sync(0xffffffffu, mx0, 1));
        mx0 = fmaxf(mx0, __shfl_xor_sync(0xffffffffu, mx0, 2));
        mx1 = fmaxf(mx1, __shfl_xor_sync(0xffffffffu, mx1, 1));
        mx1 = fmaxf(mx1, __shfl_xor_sync(0xffffffffu, mx1, 2));

        float nm0 = fmaxf(m0, mx0), nm1 = fmaxf(m1, mx1);
        float al0 = exp2f(m0 - nm0), al1 = exp2f(m1 - nm1);
        m0 = nm0; m1 = nm1;

        float sum0 = 0.f, sum1 = 0.f;
#pragma unroll
        for (int nt = 0; nt < 8; nt++) {
            s[nt][0] = exp2f(s[nt][0] - nm0);
            s[nt][1] = exp2f(s[nt][1] - nm0);
            s[nt][2] = exp2f(s[nt][2] - nm1);
            s[nt][3] = exp2f(s[nt][3] - nm1);
            sum0 += s[nt][0] + s[nt][1];
            sum1 += s[nt][2] + s[nt][3];
        }
        sum0 += __shfl_xor_sync(0xffffffffu, sum0, 1);
        sum0 += __shfl_xor_sync(0xffffffffu, sum0, 2);
        sum1 += __shfl_xor_sync(0xffffffffu, sum1, 1);
        sum1 += __shfl_xor_sync(0xffffffffu, sum1, 2);
        l0 = l0 * al0 + sum0;
        l1 = l1 * al1 + sum1;

        if (lc == 0) {
            al_s[r0] = al0;
            al_s[r0 + 8] = al1;
        }

#pragma unroll
        for (int nt = 0; nt < 8; nt++) {
            int colp = nt * 8 + 2 * lc;
            Ps[r0 * PSTR + colp]           = f2tf(s[nt][0]);
            Ps[r0 * PSTR + colp + 1]       = f2tf(s[nt][1]);
            Ps[(r0 + 8) * PSTR + colp]     = f2tf(s[nt][2]);
            Ps[(r0 + 8) * PSTR + colp + 1] = f2tf(s[nt][3]);
        }
        __syncthreads();

#pragma unroll
        for (int mt = 0; mt < 4; mt++) {
            float a0 = al_s[wm2 + mt * 16 + lr];
            float a1 = al_s[wm2 + mt * 16 + lr + 8];
#pragma unroll
            for (int nt = 0; nt < 4; nt++) {
                o[mt][nt][0] *= a0; o[mt][nt][1] *= a0;
                o[mt][nt][2] *= a1; o[mt][nt][3] *= a1;
            }
        }

        const uint32_t v_lane = vst_u + (uint32_t)(((wn2 + lb_r) * VSTR + lb_c) * 4);
        uint32_t pa[2][4][4], pb[2][2][4];
#pragma unroll
        for (int mt = 0; mt < 4; mt++)
            ldsm4(pa[0][mt], p_lane + (uint32_t)((mt * 16 * PSTR) * 4));
#pragma unroll
        for (int p = 0; p < 2; p++)
            ldsm4(pb[0][p], v_lane + (uint32_t)((p * 16 * VSTR) * 4));

#pragma unroll
        for (int ksx = 0; ksx < 8; ksx++) {
            const int cur = ksx & 1;
            if (ksx < 7) {
                const int kbn = (ksx + 1) * 8;
#pragma unroll
                for (int mt = 0; mt < 4; mt++)
                    ldsm4(pa[cur ^ 1][mt], p_lane + (uint32_t)((mt * 16 * PSTR + kbn) * 4));
#pragma unroll
                for (int p = 0; p < 2; p++)
                    ldsm4(pb[cur ^ 1][p], v_lane + (uint32_t)((p * 16 * VSTR + kbn) * 4));
            }
#pragma unroll
            for (int mt = 0; mt < 4; mt++) {
                mma_tf32(o[mt][0], pa[cur][mt], pb[cur][0]);
                mma_tf32(o[mt][1], pa[cur][mt], pb[cur][0] + 2);
                mma_tf32(o[mt][2], pa[cur][mt], pb[cur][1]);
                mma_tf32(o[mt][3], pa[cur][mt], pb[cur][1] + 2);
            }
        }
        __syncthreads();
    }
#undef ISSUE_KV

    if (lc == 0) {
        l_s[r0] = l0;
        l_s[r0 + 8] = l1;
    }
    __syncthreads();

    const int b = bh >> 4, h = bh & 15;
#pragma unroll
    for (int mt = 0; mt < 4; mt++) {
        int rloc = wm2 + mt * 16 + lr;
        int row0 = qt * FBQ + rloc;
        float il0 = 1.f / l_s[rloc];
        float il1 = 1.f / l_s[rloc + 8];
        float* out0 = ctx + (size_t)(b * S_ + row0) * H_ + h * HD_ + wn2;
        float* out1 = out0 + (size_t)8 * H_;
#pragma unroll
        for (int nt = 0; nt < 4; nt++) {
            int col = nt * 8 + 2 * lc;
            float2 v0 = { f2tff(o[mt][nt][0] * il0), f2tff(o[mt][nt][1] * il0) };
            float2 v1 = { f2tff(o[mt][nt][2] * il1), f2tff(o[mt][nt][3] * il1) };
            *(float2*)(out0 + col) = v0;
            *(float2*)(out1 + col) = v1;
        }
    }
}

// ---------------- launch ----------------
extern "C" void kernel_launch(void* const* d_in, const int* in_sizes, int n_in,
                              void* d_out, int out_size)
{
    const float* hidden = (const float*)d_in[0];
    const float* cosb   = (const float*)d_in[1];
    const float* sinb   = (const float*)d_in[2];
    // d_in[3]: attention_mask (pure causal -> implemented directly)
    const float* logn   = (const float*)d_in[4];
    const float* Wc     = (const float*)d_in[5];
    const float* bc     = (const float*)d_in[6];
    const float* Wp     = (const float*)d_in[7];
    const float* bp     = (const float*)d_in[8];
    float* out = (float*)d_out;

    float *Q, *Kt, *Vt, *ctx, *hid_tf, *wct, *wpt;
    cudaGetSymbolAddress((void**)&Q,      g_q);
    cudaGetSymbolAddress((void**)&Kt,     g_k);
    cudaGetSymbolAddress((void**)&Vt,     g_v);
    cudaGetSymbolAddress((void**)&ctx,    g_ctx);
    cudaGetSymbolAddress((void**)&hid_tf, g_hid_tf);
    cudaGetSymbolAddress((void**)&wct,    g_wct);
    cudaGetSymbolAddress((void**)&wpt,    g_wpt);

    cudaFuncSetAttribute(gemm_tf32,
                         cudaFuncAttributeMaxDynamicSharedMemorySize, GEMM_SMEM);
    cudaFuncSetAttribute(gemm_qkv,
                         cudaFuncAttributeMaxDynamicSharedMemorySize, GEMM_SMEM);
    cudaFuncSetAttribute(flash_tc,
                         cudaFuncAttributeMaxDynamicSharedMemorySize, FLASH_SMEM);

    // 0) pre-round A + transpose/round weights (one launch)
    prep_all<<<PREP_H + PREP_WC + PREP_WP, 256>>>(hidden, Wc, Wp, hid_tf, wct, wpt);

    // 1) fused QKV GEMM + rope/logn/V-transpose -> g_q, g_k, g_v
    gemm_qkv<<<dim3(QKV_N / 128, ROWS_ / 128), 256, GEMM_SMEM>>>(
        hid_tf, wct, bc, cosb, sinb, logn, Q, Kt, Vt, ROWS_, QKV_N, H_);

    // 2) flash attention -> ctx [4096, 2048]
    flash_tc<<<dim3(S_ / FBQ, B_ * NH_), 256, FLASH_SMEM>>>(Q, Kt, Vt, ctx);

    // 3) out = ctx @ Wp + bp      [4096,2048]
    gemm_tf32<<<dim3(H_ / 128, ROWS_ / 128), 256, GEMM_SMEM>>>(
        ctx, wpt, bp, out, ROWS_, H_, H_);
}

// round 14
// speedup vs baseline: 1.3604x; 1.0625x over previous
#include <cuda_runtime.h>
#include <cuda_bf16.h>
#include <math.h>
#include <stdint.h>

// Problem constants
#define B_  2
#define S_  2048
#define H_  2048
#define NH_ 16
#define HD_ 128
#define ROWS_ (B_ * S_)        // 4096
#define QKV_N (3 * H_)         // 6144

// ---------------- scratch (static device globals; no allocation) ----------------
__device__ float g_q[(size_t)B_ * NH_ * S_ * HD_];        // [b,h,s,d] tf32-rounded (log2e folded)
__device__ float g_k[(size_t)B_ * NH_ * S_ * HD_];        // [b,h,s,d] tf32-rounded
__device__ float g_v[(size_t)B_ * NH_ * S_ * HD_];        // [b,h,d,s] tf32-rounded
__device__ float g_ctx[(size_t)ROWS_ * H_];               // [b*s, h*d] tf32-rounded
__device__ float g_hid_tf[(size_t)ROWS_ * H_];            // tf32-rounded A
__device__ float g_wct[(size_t)QKV_N * H_];               // Wc^T [6144][2048] tf32
__device__ float g_wpt[(size_t)H_ * H_];                  // Wp^T [2048][2048] tf32

// ---------------- helpers ----------------
__device__ __forceinline__ uint32_t f2tf(float x) {
    uint32_t r;
    asm("cvt.rna.tf32.f32 %0, %1;" : "=r"(r) : "f"(x));
    return r;
}
__device__ __forceinline__ float f2tff(float x) { return __uint_as_float(f2tf(x)); }

__device__ __forceinline__ void mma_tf32(float* c, const uint32_t* a, const uint32_t* b) {
    asm volatile(
        "mma.sync.aligned.m16n8k8.row.col.f32.tf32.tf32.f32 "
        "{%0,%1,%2,%3}, {%4,%5,%6,%7}, {%8,%9}, {%0,%1,%2,%3};\n"
        : "+f"(c[0]), "+f"(c[1]), "+f"(c[2]), "+f"(c[3])
        : "r"(a[0]), "r"(a[1]), "r"(a[2]), "r"(a[3]),
          "r"(b[0]), "r"(b[1]));
}
__device__ __forceinline__ void ldsm4(uint32_t* r, uint32_t addr) {
    asm volatile("ldmatrix.sync.aligned.m8n8.x4.shared.b16 {%0,%1,%2,%3}, [%4];"
        : "=r"(r[0]), "=r"(r[1]), "=r"(r[2]), "=r"(r[3]) : "r"(addr));
}
__device__ __forceinline__ uint32_t smem_u32(const void* p) {
    return (uint32_t)__cvta_generic_to_shared(p);
}
__device__ __forceinline__ void cp16(uint32_t dst, const void* src) {
    asm volatile("cp.async.cg.shared.global [%0], [%1], 16;" :: "r"(dst), "l"(src));
}
__device__ __forceinline__ void cp_commit() {
    asm volatile("cp.async.commit_group;");
}
template<int N> __device__ __forceinline__ void cp_wait() {
    asm volatile("cp.async.wait_group %0;" :: "n"(N));
}

// ---------------- merged preprocessing (float4 transposes) ----------------
__device__ __forceinline__ void wtrans_body4(
    const float* __restrict__ in, float* __restrict__ out,
    int K, int N, int k0, int n0, int tid, float (*t)[33])
{
    const int x4 = tid & 7, y = tid >> 3;    // 8 float4-cols x 32 rows
    {
        float4 v = *(const float4*)(in + (size_t)(k0 + y) * N + n0 + x4 * 4);
        t[y][x4 * 4 + 0] = v.x;
        t[y][x4 * 4 + 1] = v.y;
        t[y][x4 * 4 + 2] = v.z;
        t[y][x4 * 4 + 3] = v.w;
    }
    __syncthreads();
    {
        float4 v;
        v.x = f2tff(t[x4 * 4 + 0][y]);
        v.y = f2tff(t[x4 * 4 + 1][y]);
        v.z = f2tff(t[x4 * 4 + 2][y]);
        v.w = f2tff(t[x4 * 4 + 3][y]);
        *(float4*)(out + (size_t)(n0 + y) * K + k0 + x4 * 4) = v;
    }
}

#define PREP_H 8192
#define PREP_WC 12288
#define PREP_WP 4096

__global__ __launch_bounds__(256) void prep_all(
    const float* __restrict__ hidden, const float* __restrict__ Wc,
    const float* __restrict__ Wp,
    float* __restrict__ hid_tf, float* __restrict__ wct, float* __restrict__ wpt)
{
    __shared__ float t[32][33];
    const int bid = blockIdx.x;
    if (bid < PREP_H) {
        int i = bid * 256 + threadIdx.x;
        float4 v = ((const float4*)hidden)[i];
        v.x = f2tff(v.x); v.y = f2tff(v.y); v.z = f2tff(v.z); v.w = f2tff(v.w);
        ((float4*)hid_tf)[i] = v;
    } else if (bid < PREP_H + PREP_WC) {
        int id = bid - PREP_H;
        wtrans_body4(Wc, wct, H_, QKV_N, (id & 63) * 32, (id >> 6) * 32, threadIdx.x, t);
    } else {
        int id = bid - PREP_H - PREP_WC;
        wtrans_body4(Wp, wpt, H_, H_, (id & 63) * 32, (id >> 6) * 32, threadIdx.x, t);
    }
}

// ---------------- TF32 GEMM mainloop: 128x128, BK=32, 3 stages ----------------
#define GSTR 36
#define GT_ST (128 * GSTR)
#define G_ST  (2 * GT_ST)
#define GEMM_SMEM (3 * G_ST * 4)    // 110592 B
#define TSSTR 132

// prefetch split: A-half at ks==0, B-half at ks==1 (spreads LSU bursts)
#define ISSUE_A(kt, st)                                                           \
    do {                                                                          \
        const float* Asrc = Ab + (kt) * 32;                                       \
        uint32_t au = as_u + (uint32_t)((st) * G_ST * 4);                         \
        _Pragma("unroll")                                                         \
        for (int i = 0; i < 4; i++) {                                             \
            int ch = tid + 256 * i;                                               \
            int r = ch >> 3, c2 = (ch & 7) << 2;                                  \
            cp16(au + (uint32_t)((r * GSTR + c2) * 4), Asrc + (size_t)r * K + c2);\
        }                                                                         \
    } while (0)
#define ISSUE_B(kt, st)                                                           \
    do {                                                                          \
        const float* Bsrc = Bb + (kt) * 32;                                       \
        uint32_t bu = as_u + (uint32_t)((st) * G_ST * 4) + (uint32_t)(GT_ST * 4); \
        _Pragma("unroll")                                                         \
        for (int i = 0; i < 4; i++) {                                             \
            int ch = tid + 256 * i;                                               \
            int r = ch >> 3, c2 = (ch & 7) << 2;                                  \
            cp16(bu + (uint32_t)((r * GSTR + c2) * 4), Bsrc + (size_t)r * K + c2);\
        }                                                                         \
    } while (0)

#define GEMM_MAINLOOP(Aptr, Bptr)                                                 \
    const uint32_t as_u = smem_u32(gsm);                                          \
    const int tid = threadIdx.x;                                                  \
    const int bx = blockIdx.x, by = blockIdx.y;                                   \
    const int warp = tid >> 5, lane = tid & 31;                                   \
    const int wm = (warp & 1) * 64;                                               \
    const int wn = (warp >> 1) * 32;                                              \
    const int lr = lane >> 2;                                                     \
    const int lc = lane & 3;                                                      \
    const int la_m = lane & 15;                                                   \
    const int la_k = (lane >> 4) << 2;                                            \
    const int lb_r = (lane & 7) + ((lane >> 4) << 3);                             \
    const int lb_c = ((lane >> 3) & 1) << 2;                                      \
    const uint32_t a_lane = as_u + (uint32_t)(((wm + la_m) * GSTR + la_k) * 4);   \
    const uint32_t b_lane = as_u + (uint32_t)(GT_ST * 4)                          \
                          + (uint32_t)(((wn + lb_r) * GSTR + lb_c) * 4);          \
    const float* Ab = (Aptr) + (size_t)(by * 128) * K;                            \
    const float* Bb = (Bptr) + (size_t)(bx * 128) * K;                            \
    const int KT = K >> 5;                                                        \
    ISSUE_A(0, 0); ISSUE_B(0, 0); cp_commit();                                    \
    ISSUE_A(1, 1); ISSUE_B(1, 1); cp_commit();                                    \
    float c[4][4][4];                                                             \
    _Pragma("unroll")                                                             \
    for (int mt = 0; mt < 4; mt++)                                                \
        _Pragma("unroll")                                                         \
        for (int nt = 0; nt < 4; nt++)                                            \
            _Pragma("unroll")                                                     \
            for (int j = 0; j < 4; j++) c[mt][nt][j] = 0.f;                       \
    for (int kt = 0; kt < KT; kt++) {                                             \
        cp_wait<1>();                                                             \
        __syncthreads();                                                          \
        const uint32_t stoff = (uint32_t)((kt % 3) * G_ST * 4);                   \
        const uint32_t a_st = a_lane + stoff;                                     \
        const uint32_t b_st = b_lane + stoff;                                     \
        _Pragma("unroll")                                                         \
        for (int ks = 0; ks < 4; ks++) {                                          \
            const int kb = ks * 8;                                                \
            uint32_t af[4][4], bf[4][2];                                          \
            _Pragma("unroll")                                                     \
            for (int mt = 0; mt < 4; mt++)                                        \
                ldsm4(af[mt], a_st + (uint32_t)((mt * 16 * GSTR + kb) * 4));      \
            _Pragma("unroll")                                                     \
            for (int p = 0; p < 2; p++) {                                         \
                uint32_t r[4];                                                    \
                ldsm4(r, b_st + (uint32_t)((p * 16 * GSTR + kb) * 4));            \
                bf[2 * p][0] = r[0]; bf[2 * p][1] = r[1];                         \
                bf[2 * p + 1][0] = r[2]; bf[2 * p + 1][1] = r[3];                 \
            }                                                                     \
            _Pragma("unroll")                                                     \
            for (int mt = 0; mt < 4; mt++)                                        \
                _Pragma("unroll")                                                 \
                for (int nt = 0; nt < 4; nt++)                                    \
                    mma_tf32(c[mt][nt], af[mt], bf[nt]);                          \
            if (ks == 0 && kt + 2 < KT) { ISSUE_A(kt + 2, (kt + 2) % 3); }        \
            if (ks == 1) {                                                        \
                if (kt + 2 < KT) { ISSUE_B(kt + 2, (kt + 2) % 3); }               \
                cp_commit();                                                      \
            }                                                                     \
        }                                                                         \
    }

// ---------------- plain GEMM (proj): C = A @ Bt^T + bias ----------------
__global__ __launch_bounds__(256, 2) void gemm_tf32(
    const float* __restrict__ A, const float* __restrict__ Bt,
    const float* __restrict__ bias, float* __restrict__ C,
    int M, int N, int K)
{
    extern __shared__ float gsm[];
    GEMM_MAINLOOP(A, Bt)

#pragma unroll
    for (int mt = 0; mt < 4; mt++) {
        int row = by * 128 + wm + mt * 16 + lr;
#pragma unroll
        for (int nt = 0; nt < 4; nt++) {
            int col = bx * 128 + wn + nt * 8 + 2 * lc;
            float b0 = bias[col], b1 = bias[col + 1];
            float2 v0 = { c[mt][nt][0] + b0, c[mt][nt][1] + b1 };
            float2 v1 = { c[mt][nt][2] + b0, c[mt][nt][3] + b1 };
            *(float2*)(C + (size_t)row * N + col) = v0;
            *(float2*)(C + (size_t)(row + 8) * N + col) = v1;
        }
    }
}

// ---------------- fused QKV GEMM: rope+logn for Q/K, transpose for V ----------------
__global__ __launch_bounds__(256, 2) void gemm_qkv(
    const float* __restrict__ A, const float* __restrict__ Bt,
    const float* __restrict__ bias,
    const float* __restrict__ cosb, const float* __restrict__ sinb,
    const float* __restrict__ logn,
    float* __restrict__ Qo, float* __restrict__ Ko, float* __restrict__ Vo,
    int M, int N, int K)
{
    extern __shared__ float gsm[];
    GEMM_MAINLOOP(A, Bt)

    __syncthreads();
    float* ts = gsm;                 // [128][TSSTR]
    const bool isV = (bx >= 32);

#pragma unroll
    for (int mt = 0; mt < 4; mt++) {
        int row = wm + mt * 16 + lr;
#pragma unroll
        for (int nt = 0; nt < 4; nt++) {
            int col = wn + nt * 8 + 2 * lc;
            float b0 = bias[bx * 128 + col], b1 = bias[bx * 128 + col + 1];
            float v00 = c[mt][nt][0] + b0, v01 = c[mt][nt][1] + b1;
            float v10 = c[mt][nt][2] + b0, v11 = c[mt][nt][3] + b1;
            if (!isV) {
                ts[row * TSSTR + col] = v00;
                ts[row * TSSTR + col + 1] = v01;
                ts[(row + 8) * TSSTR + col] = v10;
                ts[(row + 8) * TSSTR + col + 1] = v11;
            } else {
                ts[col * TSSTR + row] = v00;
                ts[(col + 1) * TSSTR + row] = v01;
                ts[col * TSSTR + row + 8] = v10;
                ts[(col + 1) * TSSTR + row + 8] = v11;
            }
        }
    }
    __syncthreads();

    if (!isV) {
        const bool isQ = (bx < 16);
        const int h = bx & 15;
        float* dst = isQ ? Qo : Ko;
        for (int t = tid; t < 128 * 32; t += 256) {
            int r = t >> 5, c4 = (t & 31) << 2;
            int sg = by * 128 + r;
            int b = sg >> 11;
            int s = sg & (S_ - 1);
            const float* rowp = ts + r * TSSTR;
            float4 v  = *(const float4*)(rowp + c4);
            int dro = (c4 < 64) ? (c4 + 64) : (c4 - 64);
            float4 vo = *(const float4*)(rowp + dro);
            float4 cv = *(const float4*)(cosb + (size_t)s * HD_ + c4);
            float4 sv = *(const float4*)(sinb + (size_t)s * HD_ + c4);
            float sgn = (c4 < 64) ? -1.f : 1.f;
            float4 res;
            res.x = v.x * cv.x + sgn * vo.x * sv.x;
            res.y = v.y * cv.y + sgn * vo.y * sv.y;
            res.z = v.z * cv.z + sgn * vo.z * sv.z;
            res.w = v.w * cv.w + sgn * vo.w * sv.w;
            if (isQ) {
                float ln = logn[s] * 0.08838834764831845f * 1.4426950408889634f;
                res.x *= ln; res.y *= ln; res.z *= ln; res.w *= ln;
            }
            size_t oidx = (((size_t)(b * NH_ + h) * S_ + s) << 7) + c4;
            uint4 u = { f2tf(res.x), f2tf(res.y), f2tf(res.z), f2tf(res.w) };
            *(uint4*)(dst + oidx) = u;
        }
    } else {
        const int h = bx - 32;
        const int b = by >> 4;
        const int sl0 = (by & 15) * 128;
        for (int t = tid; t < 128 * 32; t += 256) {
            int d = t >> 5, s4 = (t & 31) << 2;
            float4 v = *(const float4*)(ts + d * TSSTR + s4);
            uint4 u = { f2tf(v.x), f2tf(v.y), f2tf(v.z), f2tf(v.w) };
            size_t oidx = ((size_t)((b * NH_ + h) * HD_ + d) * S_) + sl0 + s4;
            *(uint4*)(Vo + oidx) = u;
        }
    }
}

// ---------------- Flash attention v5: 2 barriers/tile, split KV issue ----------------
#define FBQ 128
#define FBKT 64
#define KSTR 132
#define VSTR 68
#define PSTR 68
#define FK_ST (FBKT * KSTR)
#define FV_ST (HD_ * VSTR)
#define OFF_V (2 * FK_ST)
#define OFF_P (OFF_V + 2 * FV_ST)
#define OFF_AL (OFF_P + FBQ * PSTR)
#define FLASH_SMEM ((OFF_AL + 2 * FBQ) * 4)   // 173056 B

__global__ __launch_bounds__(256) void flash_tc(
    const float* __restrict__ Q, const float* __restrict__ K,
    const float* __restrict__ V, float* __restrict__ ctx)
{
    extern __shared__ float fsm[];
    uint32_t* Ps = (uint32_t*)(fsm + OFF_P);
    float* al_s = fsm + OFF_AL;
    float* l_s  = al_s + FBQ;
    const uint32_t ks_u = smem_u32(fsm);
    const uint32_t vs_u = ks_u + (uint32_t)(OFF_V * 4);
    const uint32_t ps_u = smem_u32(Ps);

    const int qt = (S_ / FBQ - 1) - blockIdx.x;
    const int bh = blockIdx.y;
    const int tid = threadIdx.x;
    const int warp = tid >> 5, lane = tid & 31;
    const int lr = lane >> 2;
    const int lc = lane & 3;

    const int la_m = lane & 15;
    const int la_k = (lane >> 4) << 2;
    const int lb_r = (lane & 7) + ((lane >> 4) << 3);
    const int lb_c = ((lane >> 3) & 1) << 2;

    const int wm2 = (warp & 1) * 64;
    const int wn2 = (warp >> 1) * 32;
    const uint32_t p_lane = ps_u + (uint32_t)(((wm2 + la_m) * PSTR + la_k) * 4);

    const float* Qb = Q + ((size_t)bh * S_ + qt * FBQ) * HD_;
    const float* Kb = K + (size_t)bh * S_ * HD_;
    const float* Vb = V + (size_t)bh * HD_ * S_;

    for (int t = tid; t < FBQ * (HD_ / 4); t += 256) {
        int r = t >> 5, c4 = (t & 31) << 2;
        *(uint4*)(fsm + r * KSTR + c4) = *(const uint4*)(Qb + (size_t)r * HD_ + c4);
    }
    __syncthreads();
    uint32_t qf[16][4];
    {
        const uint32_t q_lane = ks_u + (uint32_t)(((warp * 16 + la_m) * KSTR + la_k) * 4);
#pragma unroll
        for (int ks = 0; ks < 16; ks++)
            ldsm4(qf[ks], q_lane + (uint32_t)(ks * 8 * 4));
    }
    __syncthreads();

    const int nkt = 2 * qt + 2;

#define ISSUE_K_F(kt)                                                             \
    do {                                                                          \
        const float* ksrc = Kb + (size_t)(kt) * FBKT * HD_;                       \
        uint32_t kdst = ks_u + (uint32_t)(((kt) & 1) * FK_ST * 4);                \
        _Pragma("unroll")                                                         \
        for (int i = 0; i < 8; i++) {                                             \
            int ch = tid + 256 * i;                                               \
            int kr = ch >> 5, kc = (ch & 31) << 2;                                \
            cp16(kdst + (uint32_t)((kr * KSTR + kc) * 4),                         \
                 ksrc + (size_t)kr * HD_ + kc);                                   \
        }                                                                         \
    } while (0)
#define ISSUE_V_F(kt)                                                             \
    do {                                                                          \
        const float* vsrc = Vb + (size_t)(kt) * FBKT;                             \
        uint32_t vdst = vs_u + (uint32_t)(((kt) & 1) * FV_ST * 4);                \
        _Pragma("unroll")                                                         \
        for (int i = 0; i < 8; i++) {                                             \
            int ch = tid + 256 * i;                                               \
            int vr = ch >> 4, vc = (ch & 15) << 2;                                \
            cp16(vdst + (uint32_t)((vr * VSTR + vc) * 4),                         \
                 vsrc + (size_t)vr * S_ + vc);                                    \
        }                                                                         \
    } while (0)

    ISSUE_K_F(0);
    ISSUE_V_F(0);
    cp_commit();

    float m0 = -1e30f, m1 = -1e30f;
    float l0 = 0.f, l1 = 0.f;
    float o[4][4][4];
#pragma unroll
    for (int mt = 0; mt < 4; mt++)
#pragma unroll
        for (int nt = 0; nt < 4; nt++)
#pragma unroll
            for (int j = 0; j < 4; j++) o[mt][nt][j] = 0.f;

    const int r0 = warp * 16 + lr;
    const int g0 = qt * FBQ + r0;
    const int g1 = g0 + 8;

    for (int kt = 0; kt < nkt; kt++) {
        cp_wait<0>();                      // KV(kt) resident
        __syncthreads();                   // + all PV(kt-1) reads finished

        const bool pre = (kt + 1 < nkt);
        if (pre) { ISSUE_K_F(kt + 1); }    // write stage (kt+1)&1: safe post-barrier

        const uint32_t kst_u = ks_u + (uint32_t)((kt & 1) * FK_ST * 4);
        const uint32_t vst_u = vs_u + (uint32_t)((kt & 1) * FV_ST * 4);
        const uint32_t k_lane = kst_u + (uint32_t)((lb_r * KSTR + lb_c) * 4);

        float s[8][4];
#pragma unroll
        for (int nt = 0; nt < 8; nt++)
#pragma unroll
            for (int j = 0; j < 4; j++) s[nt][j] = 0.f;

        uint32_t kf[2][4][4];
#pragma unroll
        for (int p = 0; p < 4; p++)
            ldsm4(kf[0][p], k_lane + (uint32_t)((p * 16 * KSTR) * 4));
#pragma unroll
        for (int ksx = 0; ksx < 16; ksx++) {
            const int cur = ksx & 1;
            if (ksx < 15) {
                const int kbn = (ksx + 1) * 8;
#pragma unroll
                for (int p = 0; p < 4; p++)
                    ldsm4(kf[cur ^ 1][p], k_lane + (uint32_t)((p * 16 * KSTR + kbn) * 4));
            }
#pragma unroll
            for (int p = 0; p < 4; p++) {
                mma_tf32(s[2 * p], qf[ksx], kf[cur][p]);
                mma_tf32(s[2 * p + 1], qf[ksx], kf[cur][p] + 2);
            }
            if (ksx == 0) {                // V issue deferred past first k-step
                if (pre) { ISSUE_V_F(kt + 1); }
                cp_commit();
            }
        }

        if (kt * FBKT + FBKT - 1 > qt * FBQ + warp * 16) {
#pragma unroll
            for (int nt = 0; nt < 8; nt++) {
                int colb = kt * FBKT + nt * 8 + 2 * lc;
                if (colb > g0)     s[nt][0] = -1e30f;
                if (colb + 1 > g0) s[nt][1] = -1e30f;
                if (colb > g1)     s[nt][2] = -1e30f;
                if (colb + 1 > g1) s[nt][3] = -1e30f;
            }
        }

        float mx0 = -1e30f, mx1 = -1e30f;
#pragma unroll
        for (int nt = 0; nt < 8; nt++) {
            mx0 = fmaxf(mx0, fmaxf(s[nt][0], s[nt][1]));
            mx1 = fmaxf(mx1, fmaxf(s[nt][2], s[nt][3]));
        }
        mx0 = fmaxf(mx0, __shfl_xor_sync(0xffffffffu, mx0, 1));
        mx0 = fmaxf(mx0, __shfl_xor_sync(0xffffffffu, mx0, 2));
        mx1 = fmaxf(mx1, __shfl_xor_sync(0xffffffffu, mx1, 1));
        mx1 = fmaxf(mx1, __shfl_xor_sync(0xffffffffu, mx1, 2));

        float nm0 = fmaxf(m0, mx0), nm1 = fmaxf(m1, mx1);
        float al0 = exp2f(m0 - nm0), al1 = exp2f(m1 - nm1);
        m0 = nm0; m1 = nm1;

        float sum0 = 0.f, sum1 = 0.f;
#pragma unroll
        for (int nt = 0; nt < 8; nt++) {
            s[nt][0] = exp2f(s[nt][0] - nm0);
            s[nt][1] = exp2f(s[nt][1] - nm0);
            s[nt][2] = exp2f(s[nt][2] - nm1);
            s[nt][3] = exp2f(s[nt][3] - nm1);
            sum0 += s[nt][0] + s[nt][1];
            sum1 += s[nt][2] + s[nt][3];
        }
        sum0 += __shfl_xor_sync(0xffffffffu, sum0, 1);
        sum0 += __shfl_xor_sync(0xffffffffu, sum0, 2);
        sum1 += __shfl_xor_sync(0xffffffffu, sum1, 1);
        sum1 += __shfl_xor_sync(0xffffffffu, sum1, 2);
        l0 = l0 * al0 + sum0;
        l1 = l1 * al1 + sum1;

        if (lc == 0) {
            al_s[r0] = al0;
            al_s[r0 + 8] = al1;
        }

#pragma unroll
        for (int nt = 0; nt < 8; nt++) {
            int colp = nt * 8 + 2 * lc;
            Ps[r0 * PSTR + colp]           = f2tf(s[nt][0]);
            Ps[r0 * PSTR + colp + 1]       = f2tf(s[nt][1]);
            Ps[(r0 + 8) * PSTR + colp]     = f2tf(s[nt][2]);
            Ps[(r0 + 8) * PSTR + colp + 1] = f2tf(s[nt][3]);
        }
        __syncthreads();                   // publish P + al

#pragma unroll
        for (int mt = 0; mt < 4; mt++) {
            float a0 = al_s[wm2 + mt * 16 + lr];
            float a1 = al_s[wm2 + mt * 16 + lr + 8];
#pragma unroll
            for (int nt = 0; nt < 4; nt++) {
                o[mt][nt][0] *= a0; o[mt][nt][1] *= a0;
                o[mt][nt][2] *= a1; o[mt][nt][3] *= a1;
            }
        }

        const uint32_t v_lane = vst_u + (uint32_t)(((wn2 + lb_r) * VSTR + lb_c) * 4);
        uint32_t pa[2][4][4], pb[2][2][4];
#pragma unroll
        for (int mt = 0; mt < 4; mt++)
            ldsm4(pa[0][mt], p_lane + (uint32_t)((mt * 16 * PSTR) * 4));
#pragma unroll
        for (int p = 0; p < 2; p++)
            ldsm4(pb[0][p], v_lane + (uint32_t)((p * 16 * VSTR) * 4));

#pragma unroll
        for (int ksx = 0; ksx < 8; ksx++) {
            const int cur = ksx & 1;
            if (ksx < 7) {
                const int kbn = (ksx + 1) * 8;
#pragma unroll
                for (int mt = 0; mt < 4; mt++)
                    ldsm4(pa[cur ^ 1][mt], p_lane + (uint32_t)((mt * 16 * PSTR + kbn) * 4));
#pragma unroll
                for (int p = 0; p < 2; p++)
                    ldsm4(pb[cur ^ 1][p], v_lane + (uint32_t)((p * 16 * VSTR + kbn) * 4));
            }
#pragma unroll
            for (int mt = 0; mt < 4; mt++) {
                mma_tf32(o[mt][0], pa[cur][mt], pb[cur][0]);
                mma_tf32(o[mt][1], pa[cur][mt], pb[cur][0] + 2);
                mma_tf32(o[mt][2], pa[cur][mt], pb[cur][1]);
                mma_tf32(o[mt][3], pa[cur][mt], pb[cur][1] + 2);
            }
        }
        // no end barrier: next iteration's top barrier protects stage reuse
    }
#undef ISSUE_K_F
#undef ISSUE_V_F

    if (lc == 0) {
        l_s[r0] = l0;
        l_s[r0 + 8] = l1;
    }
    __syncthreads();

    const int b = bh >> 4, h = bh & 15;
#pragma unroll
    for (int mt = 0; mt < 4; mt++) {
        int rloc = wm2 + mt * 16 + lr;
        int row0 = qt * FBQ + rloc;
        float il0 = 1.f / l_s[rloc];
        float il1 = 1.f / l_s[rloc + 8];
        float* out0 = ctx + (size_t)(b * S_ + row0) * H_ + h * HD_ + wn2;
        float* out1 = out0 + (size_t)8 * H_;
#pragma unroll
        for (int nt = 0; nt < 4; nt++) {
            int col = nt * 8 + 2 * lc;
            float2 v0 = { f2tff(o[mt][nt][0] * il0), f2tff(o[mt][nt][1] * il0) };
            float2 v1 = { f2tff(o[mt][nt][2] * il1), f2tff(o[mt][nt][3] * il1) };
            *(float2*)(out0 + col) = v0;
            *(float2*)(out1 + col) = v1;
        }
    }
}

// ---------------- launch ----------------
extern "C" void kernel_launch(void* const* d_in, const int* in_sizes, int n_in,
                              void* d_out, int out_size)
{
    const float* hidden = (const float*)d_in[0];
    const float* cosb   = (const float*)d_in[1];
    const float* sinb   = (const float*)d_in[2];
    // d_in[3]: attention_mask (pure causal -> implemented directly)
    const float* logn   = (const float*)d_in[4];
    const float* Wc     = (const float*)d_in[5];
    const float* bc     = (const float*)d_in[6];
    const float* Wp     = (const float*)d_in[7];
    const float* bp     = (const float*)d_in[8];
    float* out = (float*)d_out;

    float *Q, *Kt, *Vt, *ctx, *hid_tf, *wct, *wpt;
    cudaGetSymbolAddress((void**)&Q,      g_q);
    cudaGetSymbolAddress((void**)&Kt,     g_k);
    cudaGetSymbolAddress((void**)&Vt,     g_v);
    cudaGetSymbolAddress((void**)&ctx,    g_ctx);
    cudaGetSymbolAddress((void**)&hid_tf, g_hid_tf);
    cudaGetSymbolAddress((void**)&wct,    g_wct);
    cudaGetSymbolAddress((void**)&wpt,    g_wpt);

    cudaFuncSetAttribute(gemm_tf32,
                         cudaFuncAttributeMaxDynamicSharedMemorySize, GEMM_SMEM);
    cudaFuncSetAttribute(gemm_qkv,
                         cudaFuncAttributeMaxDynamicSharedMemorySize, GEMM_SMEM);
    cudaFuncSetAttribute(flash_tc,
                         cudaFuncAttributeMaxDynamicSharedMemorySize, FLASH_SMEM);

    // 0) pre-round A + transpose/round weights (one launch)
    prep_all<<<PREP_H + PREP_WC + PREP_WP, 256>>>(hidden, Wc, Wp, hid_tf, wct, wpt);

    // 1) fused QKV GEMM + rope/logn/V-transpose -> g_q, g_k, g_v
    gemm_qkv<<<dim3(QKV_N / 128, ROWS_ / 128), 256, GEMM_SMEM>>>(
        hid_tf, wct, bc, cosb, sinb, logn, Q, Kt, Vt, ROWS_, QKV_N, H_);

    // 2) flash attention -> ctx [4096, 2048]
    flash_tc<<<dim3(S_ / FBQ, B_ * NH_), 256, FLASH_SMEM>>>(Q, Kt, Vt, ctx);

    // 3) out = ctx @ Wp + bp      [4096,2048]
    gemm_tf32<<<dim3(H_ / 128, ROWS_ / 128), 256, GEMM_SMEM>>>(
        ctx, wpt, bp, out, ROWS_, H_, H_);
}